// round 1
// baseline (speedup 1.0000x reference)
#include <cuda_runtime.h>
#include <cstdint>

#define NVIS 192
#define NAUD 64
#define TT   128
#define FDIM 1024
#define C    128
#define EE   262144
#define NN   32768           // total nodes
#define NVT  24576           // NVIS * TT
#define MOUT 8192            // output rows

// ---------------- device scratch (static allocation only) ----------------
__device__ float g_x[NN * C];
__device__ float g_xag[NN * C];
__device__ float g_a[NN * C];
__device__ float g_ares[NN];
__device__ float g_xv2[NN * C];
__device__ float g_u[NN * C];
__device__ float g_v[NN * C];
__device__ float g_h[NN * C];
__device__ float g_s[NN * C];
__device__ int   g_cnt[3][NN];
__device__ int2  g_elist[9][EE];   // 0:vpa 1:audio 2:acv 3:m1 4:m2 5:m3 6..8: m1..m3 dst-in-output
__device__ int   g_count[9];

// ---------------- zero kernels ----------------
__global__ void zero_all(float4* out4) {
    const long A4 = (long)NN * C / 4;           // 1048576
    const long O4 = (long)MOUT * C / 4;         // 262144
    const long C4 = 3L * NN / 4;                // 24576
    const long total = 3 * A4 + O4 + C4;
    float4 z = make_float4(0.f, 0.f, 0.f, 0.f);
    for (long i = blockIdx.x * (long)blockDim.x + threadIdx.x; i < total;
         i += (long)gridDim.x * blockDim.x) {
        if (i < A4)            ((float4*)g_xag)[i] = z;
        else if (i < 2 * A4)   ((float4*)g_a)[i - A4] = z;
        else if (i < 3 * A4)   ((float4*)g_xv2)[i - 2 * A4] = z;
        else if (i < 3 * A4 + O4) out4[i - 3 * A4] = z;
        else                   ((float4*)g_cnt)[i - 3 * A4 - O4] = z;
    }
    if (blockIdx.x == 0 && threadIdx.x < 9) g_count[threadIdx.x] = 0;
}

__global__ void zero_hs() {
    const long A4 = (long)NN * C / 4;
    float4 z = make_float4(0.f, 0.f, 0.f, 0.f);
    for (long i = blockIdx.x * (long)blockDim.x + threadIdx.x; i < 2 * A4;
         i += (long)gridDim.x * blockDim.x) {
        if (i < A4) ((float4*)g_h)[i] = z;
        else        ((float4*)g_s)[i - A4] = z;
    }
}

// ---------------- edge classification / compaction ----------------
__global__ void classify_k(const int* __restrict__ ei, const int* __restrict__ attr) {
    int e = blockIdx.x * blockDim.x + threadIdx.x;
    if (e >= EE) return;
    int a = attr[e];
    int2 p = make_int2(ei[e], ei[EE + e]);
    if (a == -3) { int i = atomicAdd(&g_count[0], 1); g_elist[0][i] = p; }
    if (a == -2) { int i = atomicAdd(&g_count[1], 1); g_elist[1][i] = p; }
    if (a == 3)  { int i = atomicAdd(&g_count[2], 1); g_elist[2][i] = p; }
    bool m1 = (a >= 0) && (a <= 1);
    bool m2 = (a >= -1) && (a <= 0);
    bool m3 = (a >= -1) && (a <= 1);
    bool dout = (p.y < NVT) && (((p.y >> 7) % 3) == 0);
    if (m1) { int i = atomicAdd(&g_count[3], 1); g_elist[3][i] = p; atomicAdd(&g_cnt[0][p.y], 1);
              if (dout) { int j = atomicAdd(&g_count[6], 1); g_elist[6][j] = p; } }
    if (m2) { int i = atomicAdd(&g_count[4], 1); g_elist[4][i] = p; atomicAdd(&g_cnt[1][p.y], 1);
              if (dout) { int j = atomicAdd(&g_count[7], 1); g_elist[7][j] = p; } }
    if (m3) { int i = atomicAdd(&g_count[5], 1); g_elist[5][i] = p; atomicAdd(&g_cnt[2][p.y], 1);
              if (dout) { int j = atomicAdd(&g_count[8], 1); g_elist[8][j] = p; } }
}

// ---------------- projection GEMM: g_x = [x_visual;x_audio] @ W + b ----------------
// grid (2, 512), block 256. BM=BN=64, BK=16, thread tile 4x4.
__global__ __launch_bounds__(256) void proj_gemm(
    const float* __restrict__ xv, const float* __restrict__ xa,
    const float* __restrict__ Wv, const float* __restrict__ bv,
    const float* __restrict__ Wa, const float* __restrict__ ba) {
    __shared__ float As[16][68];
    __shared__ float Bs[16][68];
    int rowBase = blockIdx.y * 64;
    int colBase = blockIdx.x * 64;
    bool vis = rowBase < NVT;
    const float* A = vis ? (xv + (size_t)rowBase * FDIM)
                         : (xa + (size_t)(rowBase - NVT) * FDIM);
    const float* W = vis ? Wv : Wa;
    const float* bias = vis ? bv : ba;
    int tid = threadIdx.x;
    int ar = tid >> 2, ak = (tid & 3) * 4;
    int bk = tid >> 4, bc = (tid & 15) * 4;
    int ty = tid >> 4, tx = tid & 15;
    float acc[4][4] = {};
    for (int kt = 0; kt < FDIM; kt += 16) {
        float4 a4 = *(const float4*)(A + (size_t)ar * FDIM + kt + ak);
        float4 b4 = *(const float4*)(W + (size_t)(kt + bk) * C + colBase + bc);
        As[ak + 0][ar] = a4.x; As[ak + 1][ar] = a4.y;
        As[ak + 2][ar] = a4.z; As[ak + 3][ar] = a4.w;
        *(float4*)&Bs[bk][bc] = b4;
        __syncthreads();
#pragma unroll
        for (int k = 0; k < 16; k++) {
            float4 av = *(float4*)&As[k][ty * 4];
            float4 bvv = *(float4*)&Bs[k][tx * 4];
            float ra[4] = {av.x, av.y, av.z, av.w};
            float rb[4] = {bvv.x, bvv.y, bvv.z, bvv.w};
#pragma unroll
            for (int i = 0; i < 4; i++)
#pragma unroll
                for (int j = 0; j < 4; j++) acc[i][j] += ra[i] * rb[j];
        }
        __syncthreads();
    }
#pragma unroll
    for (int i = 0; i < 4; i++) {
        int row = rowBase + ty * 4 + i;
#pragma unroll
        for (int j = 0; j < 4; j++) {
            int col = colBase + tx * 4 + j;
            g_x[(size_t)row * C + col] = acc[i][j] + bias[col];
        }
    }
}

// ---------------- node GEMM: Co[M,128] = (reluA? relu(A):A) @ B (+bias) ----------------
// grid (2, NN/64), block 256.
__global__ __launch_bounds__(256) void node_gemm(
    const float* __restrict__ A, const float* __restrict__ B,
    const float* __restrict__ bias, float* __restrict__ Co, int reluA) {
    __shared__ float As[16][68];
    __shared__ float Bs[16][68];
    int rowBase = blockIdx.y * 64;
    int colBase = blockIdx.x * 64;
    int tid = threadIdx.x;
    int ar = tid >> 2, ak = (tid & 3) * 4;
    int bk = tid >> 4, bc = (tid & 15) * 4;
    int ty = tid >> 4, tx = tid & 15;
    float acc[4][4] = {};
    const float* Arow = A + (size_t)(rowBase + ar) * C;
    for (int kt = 0; kt < C; kt += 16) {
        float4 a4 = *(const float4*)(Arow + kt + ak);
        if (reluA) {
            a4.x = fmaxf(a4.x, 0.f); a4.y = fmaxf(a4.y, 0.f);
            a4.z = fmaxf(a4.z, 0.f); a4.w = fmaxf(a4.w, 0.f);
        }
        float4 b4 = *(const float4*)(B + (size_t)(kt + bk) * C + colBase + bc);
        As[ak + 0][ar] = a4.x; As[ak + 1][ar] = a4.y;
        As[ak + 2][ar] = a4.z; As[ak + 3][ar] = a4.w;
        *(float4*)&Bs[bk][bc] = b4;
        __syncthreads();
#pragma unroll
        for (int k = 0; k < 16; k++) {
            float4 av = *(float4*)&As[k][ty * 4];
            float4 bv = *(float4*)&Bs[k][tx * 4];
            float ra[4] = {av.x, av.y, av.z, av.w};
            float rb[4] = {bv.x, bv.y, bv.z, bv.w};
#pragma unroll
            for (int i = 0; i < 4; i++)
#pragma unroll
                for (int j = 0; j < 4; j++) acc[i][j] += ra[i] * rb[j];
        }
        __syncthreads();
    }
#pragma unroll
    for (int i = 0; i < 4; i++) {
        int row = rowBase + ty * 4 + i;
#pragma unroll
        for (int j = 0; j < 4; j++) {
            int col = colBase + tx * 4 + j;
            float vv = acc[i][j];
            if (bias) vv += bias[col];
            Co[(size_t)row * C + col] = vv;
        }
    }
}

// ---------------- edge GEMM: z=relu(u[d]+v[s]-v[d]); w=z@W2+b2; atomicMax -> Out[d] ----
// block 256, tile = 64 edges x 128 cols, grid-stride over tiles.
__global__ __launch_bounds__(256) void edge_gemm(
    int li, const float* __restrict__ W2, const float* __restrict__ b2,
    const float* __restrict__ U, const float* __restrict__ V,
    float* __restrict__ Out) {
    __shared__ float Zs[16][68];
    __shared__ float Bs[16][132];
    __shared__ int2 sd[64];
    __shared__ float bsh[128];
    int cnt = g_count[li];
    int tid = threadIdx.x;
    int ty = tid >> 4, tx = tid & 15;
    int zr = tid >> 2, zk = (tid & 3) * 4;
    int bk = tid >> 4, bc = (tid & 15) * 8;
    if (tid < 128) bsh[tid] = b2[tid];
    for (int tile = blockIdx.x; tile * 64 < cnt; tile += gridDim.x) {
        int eb = tile * 64;
        if (tid < 64) {
            int e = eb + tid;
            sd[tid] = (e < cnt) ? g_elist[li][e] : make_int2(0, -1);
        }
        __syncthreads();
        int2 p = sd[zr];
        int sidx = (p.y >= 0) ? p.x : 0;
        int didx = (p.y >= 0) ? p.y : 0;
        const float* urow = U + (size_t)didx * C;
        const float* vsr = V + (size_t)sidx * C;
        const float* vdr = V + (size_t)didx * C;
        float acc[4][8] = {};
        for (int kt = 0; kt < C; kt += 16) {
            float4 u4 = *(const float4*)(urow + kt + zk);
            float4 a4 = *(const float4*)(vsr + kt + zk);
            float4 d4 = *(const float4*)(vdr + kt + zk);
            Zs[zk + 0][zr] = fmaxf(u4.x + a4.x - d4.x, 0.f);
            Zs[zk + 1][zr] = fmaxf(u4.y + a4.y - d4.y, 0.f);
            Zs[zk + 2][zr] = fmaxf(u4.z + a4.z - d4.z, 0.f);
            Zs[zk + 3][zr] = fmaxf(u4.w + a4.w - d4.w, 0.f);
            *(float4*)&Bs[bk][bc]     = *(const float4*)(W2 + (size_t)(kt + bk) * C + bc);
            *(float4*)&Bs[bk][bc + 4] = *(const float4*)(W2 + (size_t)(kt + bk) * C + bc + 4);
            __syncthreads();
#pragma unroll
            for (int k = 0; k < 16; k++) {
                float4 zv = *(float4*)&Zs[k][ty * 4];
                float4 b0 = *(float4*)&Bs[k][tx * 8];
                float4 b1 = *(float4*)&Bs[k][tx * 8 + 4];
                float ra[4] = {zv.x, zv.y, zv.z, zv.w};
                float rb[8] = {b0.x, b0.y, b0.z, b0.w, b1.x, b1.y, b1.z, b1.w};
#pragma unroll
                for (int i = 0; i < 4; i++)
#pragma unroll
                    for (int j = 0; j < 8; j++) acc[i][j] += ra[i] * rb[j];
            }
            __syncthreads();
        }
#pragma unroll
        for (int i = 0; i < 4; i++) {
            int2 q = sd[ty * 4 + i];
            if (q.y < 0) continue;
            unsigned int* orow = (unsigned int*)(Out + (size_t)q.y * C);
#pragma unroll
            for (int j = 0; j < 8; j++) {
                int c = tx * 8 + j;
                float val = acc[i][j] + bsh[c];
                if (val > 0.f) atomicMax(orow + c, __float_as_uint(val));
            }
        }
        __syncthreads();
    }
}

// ---------------- warp-per-edge aggregations ----------------
__global__ void agg_vpa() {  // xa_g[d] = max(0, max over vpa edges of x[s]+x[d])
    int cnt = g_count[0];
    int nw = gridDim.x * (blockDim.x >> 5);
    int w = blockIdx.x * (blockDim.x >> 5) + (threadIdx.x >> 5);
    int lane = threadIdx.x & 31;
    for (int e = w; e < cnt; e += nw) {
        int2 p = g_elist[0][e];
        float4 a = *(const float4*)(g_x + (size_t)p.x * C + lane * 4);
        float4 b = *(const float4*)(g_x + (size_t)p.y * C + lane * 4);
        unsigned int* o = (unsigned int*)(g_xag + (size_t)p.y * C + lane * 4);
        float m;
        m = a.x + b.x; if (m > 0.f) atomicMax(o + 0, __float_as_uint(m));
        m = a.y + b.y; if (m > 0.f) atomicMax(o + 1, __float_as_uint(m));
        m = a.z + b.z; if (m > 0.f) atomicMax(o + 2, __float_as_uint(m));
        m = a.w + b.w; if (m > 0.f) atomicMax(o + 3, __float_as_uint(m));
    }
}

__global__ void ares_k(const float* __restrict__ fcW, const float* __restrict__ fcb) {
    int n = blockIdx.x * (blockDim.x >> 5) + (threadIdx.x >> 5);
    if (n >= NN) return;
    int lane = threadIdx.x & 31;
    float4 a4 = *(const float4*)(g_a + (size_t)n * C + lane * 4);
    float4 w4 = *(const float4*)(fcW + lane * 4);
    float s = a4.x * w4.x + a4.y * w4.y + a4.z * w4.z + a4.w * w4.w;
#pragma unroll
    for (int o = 16; o; o >>= 1) s += __shfl_xor_sync(0xffffffffu, s, o);
    if (lane == 0) g_ares[n] = s + fcb[0];
}

__global__ void agg_acv() {  // xv2[d] += ares[s]*x[s] + x[d] over acv edges
    int cnt = g_count[2];
    int nw = gridDim.x * (blockDim.x >> 5);
    int w = blockIdx.x * (blockDim.x >> 5) + (threadIdx.x >> 5);
    int lane = threadIdx.x & 31;
    for (int e = w; e < cnt; e += nw) {
        int2 p = g_elist[2][e];
        float wgt = g_ares[p.x];
        float4 a = *(const float4*)(g_x + (size_t)p.x * C + lane * 4);
        float4 b = *(const float4*)(g_x + (size_t)p.y * C + lane * 4);
        float* o = g_xv2 + (size_t)p.y * C + lane * 4;
        atomicAdd(o + 0, wgt * a.x + b.x);
        atomicAdd(o + 1, wgt * a.y + b.y);
        atomicAdd(o + 2, wgt * a.z + b.z);
        atomicAdd(o + 3, wgt * a.w + b.w);
    }
}

__global__ void agg_sage(int li) {  // s[d] += h[s] over out-filtered edges
    int cnt = g_count[li];
    int nw = gridDim.x * (blockDim.x >> 5);
    int w = blockIdx.x * (blockDim.x >> 5) + (threadIdx.x >> 5);
    int lane = threadIdx.x & 31;
    for (int e = w; e < cnt; e += nw) {
        int2 p = g_elist[li][e];
        float4 hv = *(const float4*)(g_h + (size_t)p.x * C + lane * 4);
        float* o = g_s + (size_t)p.y * C + lane * 4;
        atomicAdd(o + 0, hv.x);
        atomicAdd(o + 1, hv.y);
        atomicAdd(o + 2, hv.z);
        atomicAdd(o + 3, hv.w);
    }
}

// ---------------- final gathered GEMM over 8192 output rows ----------------
// out[r] += relu( (s[n]/cnt)@Wl + bl + h[n]@Wr ), n = (r>>7)*384 + (r&127)
// grid (2, 128), block 256.
__global__ __launch_bounds__(256) void final_gemm(
    const float* __restrict__ Wl, const float* __restrict__ bl,
    const float* __restrict__ Wr, int branch, float* __restrict__ out) {
    __shared__ float As[16][68];
    __shared__ float Bs[16][68];
    int rowBase = blockIdx.y * 64;
    int colBase = blockIdx.x * 64;
    int tid = threadIdx.x;
    int ar = tid >> 2, ak = (tid & 3) * 4;
    int bk = tid >> 4, bc = (tid & 15) * 4;
    int ty = tid >> 4, tx = tid & 15;
    int r = rowBase + ar;
    int n = (r >> 7) * 384 + (r & 127);
    int cv = g_cnt[branch][n];
    float inv = 1.0f / (float)(cv > 1 ? cv : 1);
    float acc[4][4] = {};
    for (int kt = 0; kt < 256; kt += 16) {
        const float* Arow;
        float scale;
        if (kt < 128) { Arow = g_s + (size_t)n * C + kt; scale = inv; }
        else          { Arow = g_h + (size_t)n * C + kt - 128; scale = 1.0f; }
        float4 a4 = *(const float4*)(Arow + ak);
        const float* Brow = (kt + bk < 128) ? (Wl + (size_t)(kt + bk) * C)
                                            : (Wr + (size_t)(kt + bk - 128) * C);
        float4 b4 = *(const float4*)(Brow + colBase + bc);
        As[ak + 0][ar] = a4.x * scale; As[ak + 1][ar] = a4.y * scale;
        As[ak + 2][ar] = a4.z * scale; As[ak + 3][ar] = a4.w * scale;
        *(float4*)&Bs[bk][bc] = b4;
        __syncthreads();
#pragma unroll
        for (int k = 0; k < 16; k++) {
            float4 av = *(float4*)&As[k][ty * 4];
            float4 bv = *(float4*)&Bs[k][tx * 4];
            float ra[4] = {av.x, av.y, av.z, av.w};
            float rb[4] = {bv.x, bv.y, bv.z, bv.w};
#pragma unroll
            for (int i = 0; i < 4; i++)
#pragma unroll
                for (int j = 0; j < 4; j++) acc[i][j] += ra[i] * rb[j];
        }
        __syncthreads();
    }
#pragma unroll
    for (int i = 0; i < 4; i++) {
        int row = rowBase + ty * 4 + i;
#pragma unroll
        for (int j = 0; j < 4; j++) {
            int col = colBase + tx * 4 + j;
            float vv = fmaxf(acc[i][j] + bl[col], 0.f);
            out[(size_t)row * C + col] += vv;
        }
    }
}

// ---------------- launch ----------------
extern "C" void kernel_launch(void* const* d_in, const int* in_sizes, int n_in,
                              void* d_out, int out_size) {
    (void)in_sizes; (void)n_in; (void)out_size;
    const float* xv    = (const float*)d_in[0];
    const float* xa    = (const float*)d_in[1];
    const float* W011  = (const float*)d_in[2];
    const float* b011  = (const float*)d_in[3];
    const float* W012  = (const float*)d_in[4];
    const float* b012  = (const float*)d_in[5];
    const float* ecA_W1 = (const float*)d_in[6];
    const float* ecA_b1 = (const float*)d_in[7];
    const float* ecA_W2 = (const float*)d_in[8];
    const float* ecA_b2 = (const float*)d_in[9];
    const float* sage_Wl = (const float*)d_in[22];
    const float* sage_bl = (const float*)d_in[23];
    const float* sage_Wr = (const float*)d_in[24];
    const float* fc_W = (const float*)d_in[25];
    const float* fc_b = (const float*)d_in[26];
    const int* edge_index = (const int*)d_in[27];
    const int* edge_attr  = (const int*)d_in[28];
    float* out = (float*)d_out;

    float *pxag, *pxv2, *pa, *pu, *pv, *ph;
    cudaGetSymbolAddress((void**)&pxag, g_xag);
    cudaGetSymbolAddress((void**)&pxv2, g_xv2);
    cudaGetSymbolAddress((void**)&pa, g_a);
    cudaGetSymbolAddress((void**)&pu, g_u);
    cudaGetSymbolAddress((void**)&pv, g_v);
    cudaGetSymbolAddress((void**)&ph, g_h);

    // stage 0: zero + compact + project
    zero_all<<<8192, 256>>>((float4*)d_out);
    classify_k<<<(EE + 255) / 256, 256>>>(edge_index, edge_attr);
    proj_gemm<<<dim3(2, NN / 64), 256>>>(xv, xa, W011, b011, W012, b012);

    // stage 1: Visual_Add_Audio max-agg
    agg_vpa<<<2048, 256>>>();

    // stage 2: ecA EdgeConv on xa_g -> a, then a_res
    node_gemm<<<dim3(2, NN / 64), 256>>>(pxag, ecA_W1, ecA_b1, pu, 0);
    node_gemm<<<dim3(2, NN / 64), 256>>>(pxag, ecA_W1 + C * C, nullptr, pv, 0);
    edge_gemm<<<1024, 256>>>(1, ecA_W2, ecA_b2, pu, pv, pa);
    ares_k<<<NN / 8, 256>>>(fc_W, fc_b);

    // stage 3: weighted sum-agg -> xv2 (relu applied at consumption)
    agg_acv<<<2048, 256>>>();

    // stage 4: three EdgeConv+SAGE branches
    for (int k = 0; k < 3; k++) {
        const float* W1 = (const float*)d_in[10 + 4 * k];
        const float* b1 = (const float*)d_in[11 + 4 * k];
        const float* W2 = (const float*)d_in[12 + 4 * k];
        const float* b2 = (const float*)d_in[13 + 4 * k];
        zero_hs<<<8192, 256>>>();
        node_gemm<<<dim3(2, NN / 64), 256>>>(pxv2, W1, b1, pu, 1);
        node_gemm<<<dim3(2, NN / 64), 256>>>(pxv2, W1 + C * C, nullptr, pv, 1);
        edge_gemm<<<1024, 256>>>(3 + k, W2, b2, pu, pv, ph);
        agg_sage<<<2048, 256>>>(6 + k);
        final_gemm<<<dim3(2, MOUT / 64), 256>>>(sage_Wl, sage_bl, sage_Wr, k, out);
    }
}

// round 4
// speedup vs baseline: 1.2765x; 1.2765x over previous
#include <cuda_runtime.h>
#include <cuda_bf16.h>
#include <cstdint>

#define NVIS 192
#define NAUD 64
#define TT   128
#define FDIM 1024
#define C    128
#define EE   262144
#define NN   32768
#define NVT  24576
#define MOUT 8192

// smem tile geometry: 4 planes (Ahi, Alo, Bhi, Blo), each 128 rows x 64 bf16x2 words,
// row stride 68 words (272B) -> conflict-free fragment loads.
#define RSW   68
#define PLANE (128 * RSW)          // words per plane
#define SMEM_BYTES (4 * PLANE * 4) // 139264

// ---------------- helpers ----------------
__device__ __forceinline__ void split2(float x, float y, uint32_t& hi, uint32_t& lo) {
    __nv_bfloat16 hx = __float2bfloat16(x), hy = __float2bfloat16(y);
    __nv_bfloat16 lx = __float2bfloat16(x - __bfloat162float(hx));
    __nv_bfloat16 ly = __float2bfloat16(y - __bfloat162float(hy));
    hi = (uint32_t)*(uint16_t*)&hx | ((uint32_t)*(uint16_t*)&hy << 16);
    lo = (uint32_t)*(uint16_t*)&lx | ((uint32_t)*(uint16_t*)&ly << 16);
}

__device__ __forceinline__ void mma_bf16(float* c, const uint32_t* a, uint32_t b0, uint32_t b1) {
    asm volatile(
        "mma.sync.aligned.m16n8k16.row.col.f32.bf16.bf16.f32 "
        "{%0,%1,%2,%3}, {%4,%5,%6,%7}, {%8,%9}, {%0,%1,%2,%3};"
        : "+f"(c[0]), "+f"(c[1]), "+f"(c[2]), "+f"(c[3])
        : "r"(a[0]), "r"(a[1]), "r"(a[2]), "r"(a[3]), "r"(b0), "r"(b1));
}

// 128x128x128 tile GEMM: C += A @ B^T with 3-pass bf16 split.
// A planes: [row][kpair] hi/lo; B planes: [n][kpair] hi/lo. acc[mt][nt][4].
__device__ __forceinline__ void gemm_tile(const uint32_t* sw, float acc[4][4][4]) {
    int lane = threadIdx.x & 31, wid = threadIdx.x >> 5;
    int wm = wid & 1, wn = wid >> 1;      // warp grid 2(m) x 4(n): 64 rows x 32 cols each
    int g = lane >> 2, t = lane & 3;
    const uint32_t* Ah = sw;
    const uint32_t* Al = sw + PLANE;
    const uint32_t* Bh = sw + 2 * PLANE;
    const uint32_t* Bl = sw + 3 * PLANE;
#pragma unroll
    for (int ks = 0; ks < 8; ks++) {
        int kb = ks * 8 + t;
        uint32_t bh[4][2], bl[4][2];
#pragma unroll
        for (int nt = 0; nt < 4; nt++) {
            int n0 = (wn * 32 + nt * 8 + g) * RSW;
            bh[nt][0] = Bh[n0 + kb];     bh[nt][1] = Bh[n0 + kb + 4];
            bl[nt][0] = Bl[n0 + kb];     bl[nt][1] = Bl[n0 + kb + 4];
        }
#pragma unroll
        for (int mt = 0; mt < 4; mt++) {
            int r0 = (wm * 64 + mt * 16 + g) * RSW;
            uint32_t ah[4], al[4];
            ah[0] = Ah[r0 + kb];            ah[1] = Ah[r0 + 8 * RSW + kb];
            ah[2] = Ah[r0 + kb + 4];        ah[3] = Ah[r0 + 8 * RSW + kb + 4];
            al[0] = Al[r0 + kb];            al[1] = Al[r0 + 8 * RSW + kb];
            al[2] = Al[r0 + kb + 4];        al[3] = Al[r0 + 8 * RSW + kb + 4];
#pragma unroll
            for (int nt = 0; nt < 4; nt++) {
                mma_bf16(acc[mt][nt], ah, bh[nt][0], bh[nt][1]);
                mma_bf16(acc[mt][nt], ah, bl[nt][0], bl[nt][1]);
                mma_bf16(acc[mt][nt], al, bh[nt][0], bh[nt][1]);
            }
        }
    }
}

// fill B planes from W[128 k-rows][128 n-cols] row-major (transpose into [n][k])
__device__ __forceinline__ void fill_B(uint32_t* sw, const float* __restrict__ W) {
    int tid = threadIdx.x;
#pragma unroll
    for (int it = 0; it < 8; it++) {
        int tk = tid + it * 256;
        int j = tk >> 5, ng = tk & 31;   // j: kpair 0..63, n = 4*ng
        int n = ng * 4;
        float4 w0 = *(const float4*)(W + (size_t)(2 * j) * C + n);
        float4 w1 = *(const float4*)(W + (size_t)(2 * j + 1) * C + n);
        float p0[4] = {w0.x, w0.y, w0.z, w0.w};
        float p1[4] = {w1.x, w1.y, w1.z, w1.w};
#pragma unroll
        for (int c2 = 0; c2 < 4; c2++) {
            uint32_t h, l;
            split2(p0[c2], p1[c2], h, l);
            sw[2 * PLANE + (n + c2) * RSW + j] = h;
            sw[3 * PLANE + (n + c2) * RSW + j] = l;
        }
    }
}

// fill one 64-k half of A row r from 16 floats x4 in src (with optional relu)
__device__ __forceinline__ void fill_A_row(uint32_t* sw, int r, int kh,
                                           const float* __restrict__ src, int relu) {
    uint32_t* aH = sw + r * RSW + kh / 2;
    uint32_t* aL = aH + PLANE;
#pragma unroll 4
    for (int k = 0; k < 64; k += 4) {
        float4 v = *(const float4*)(src + k);
        if (relu) { v.x = fmaxf(v.x, 0.f); v.y = fmaxf(v.y, 0.f); v.z = fmaxf(v.z, 0.f); v.w = fmaxf(v.w, 0.f); }
        uint32_t h0, l0, h1, l1;
        split2(v.x, v.y, h0, l0);
        split2(v.z, v.w, h1, l1);
        aH[k / 2] = h0; aH[k / 2 + 1] = h1;
        aL[k / 2] = l0; aL[k / 2 + 1] = l1;
    }
}

// ---------------- device scratch ----------------
__device__ float g_x[NN * C];
__device__ float g_xag[NN * C];
__device__ float g_a[NN * C];
__device__ float g_ares[NN];
__device__ float g_xv2[NN * C];
__device__ float g_u[NN * C];
__device__ float g_v[NN * C];
__device__ float g_h[NN * C];
__device__ float g_s[NN * C];
__device__ int   g_cnt[3][NN];
__device__ int2  g_elist[9][EE];
__device__ int   g_count[9];

// ---------------- zero / classify ----------------
__global__ void zero_all(float4* out4) {
    const long A4 = (long)NN * C / 4;
    const long O4 = (long)MOUT * C / 4;
    const long C4 = 3L * NN / 4;
    const long total = 3 * A4 + O4 + C4;
    float4 z = make_float4(0.f, 0.f, 0.f, 0.f);
    for (long i = blockIdx.x * (long)blockDim.x + threadIdx.x; i < total;
         i += (long)gridDim.x * blockDim.x) {
        if (i < A4)               ((float4*)g_xag)[i] = z;
        else if (i < 2 * A4)      ((float4*)g_a)[i - A4] = z;
        else if (i < 3 * A4)      ((float4*)g_xv2)[i - 2 * A4] = z;
        else if (i < 3 * A4 + O4) out4[i - 3 * A4] = z;
        else                      ((float4*)g_cnt)[i - 3 * A4 - O4] = z;
    }
    if (blockIdx.x == 0 && threadIdx.x < 9) g_count[threadIdx.x] = 0;
}
__global__ void zero_hs() {
    const long A4 = (long)NN * C / 4;
    float4 z = make_float4(0.f, 0.f, 0.f, 0.f);
    for (long i = blockIdx.x * (long)blockDim.x + threadIdx.x; i < 2 * A4;
         i += (long)gridDim.x * blockDim.x) {
        if (i < A4) ((float4*)g_h)[i] = z;
        else        ((float4*)g_s)[i - A4] = z;
    }
}
__global__ void classify_k(const int* __restrict__ ei, const int* __restrict__ attr) {
    int e = blockIdx.x * blockDim.x + threadIdx.x;
    if (e >= EE) return;
    int a = attr[e];
    int2 p = make_int2(ei[e], ei[EE + e]);
    if (a == -3) { int i = atomicAdd(&g_count[0], 1); g_elist[0][i] = p; }
    if (a == -2) { int i = atomicAdd(&g_count[1], 1); g_elist[1][i] = p; }
    if (a == 3)  { int i = atomicAdd(&g_count[2], 1); g_elist[2][i] = p; }
    bool m1 = (a >= 0) && (a <= 1);
    bool m2 = (a >= -1) && (a <= 0);
    bool m3 = (a >= -1) && (a <= 1);
    bool dout = (p.y < NVT) && (((p.y >> 7) % 3) == 0);
    if (m1) { int i = atomicAdd(&g_count[3], 1); g_elist[3][i] = p; atomicAdd(&g_cnt[0][p.y], 1);
              if (dout) { int j = atomicAdd(&g_count[6], 1); g_elist[6][j] = p; } }
    if (m2) { int i = atomicAdd(&g_count[4], 1); g_elist[4][i] = p; atomicAdd(&g_cnt[1][p.y], 1);
              if (dout) { int j = atomicAdd(&g_count[7], 1); g_elist[7][j] = p; } }
    if (m3) { int i = atomicAdd(&g_count[5], 1); g_elist[5][i] = p; atomicAdd(&g_cnt[2][p.y], 1);
              if (dout) { int j = atomicAdd(&g_count[8], 1); g_elist[8][j] = p; } }
}

// ---------------- mma GEMM kernels ----------------

// proj: g_x[32768,128] = [xv;xa] @ W + b  (K=1024 in 8 chunks)
__global__ __launch_bounds__(256, 1) void proj_mma(
    const float* __restrict__ xv, const float* __restrict__ xa,
    const float* __restrict__ Wv, const float* __restrict__ bv,
    const float* __restrict__ Wa, const float* __restrict__ ba) {
    extern __shared__ uint32_t sw[];
    int rowBase = blockIdx.x * 128;
    bool vis = rowBase < NVT;
    const float* X = vis ? (xv + (size_t)rowBase * FDIM) : (xa + (size_t)(rowBase - NVT) * FDIM);
    const float* W = vis ? Wv : Wa;
    const float* bias = vis ? bv : ba;
    int tid = threadIdx.x;
    int r = tid >> 1, kh = (tid & 1) * 64;
    float acc[4][4][4] = {};
    for (int kt = 0; kt < FDIM; kt += 128) {
        fill_A_row(sw, r, kh, X + (size_t)r * FDIM + kt + kh, 0);
        fill_B(sw, W + (size_t)kt * C);
        __syncthreads();
        gemm_tile(sw, acc);
        __syncthreads();
    }
    int lane = tid & 31, wid = tid >> 5, wm = wid & 1, wn = wid >> 1;
    int g = lane >> 2, t = lane & 3;
#pragma unroll
    for (int mt = 0; mt < 4; mt++) {
        int row = rowBase + wm * 64 + mt * 16 + g;
#pragma unroll
        for (int nt = 0; nt < 4; nt++) {
            int col = wn * 32 + nt * 8 + 2 * t;
            float2 v0 = make_float2(acc[mt][nt][0] + bias[col], acc[mt][nt][1] + bias[col + 1]);
            float2 v1 = make_float2(acc[mt][nt][2] + bias[col], acc[mt][nt][3] + bias[col + 1]);
            *(float2*)(g_x + (size_t)row * C + col) = v0;
            *(float2*)(g_x + (size_t)(row + 8) * C + col) = v1;
        }
    }
}

// node dual: Ou = act(A)@W1[0:128]+bias, Ov = act(A)@W1[128:256]
__global__ __launch_bounds__(256, 1) void node_dual_mma(
    const float* __restrict__ A, const float* __restrict__ W1,
    const float* __restrict__ bias, float* __restrict__ Ou, float* __restrict__ Ov, int relu) {
    extern __shared__ uint32_t sw[];
    int rowBase = blockIdx.x * 128;
    int tid = threadIdx.x;
    int r = tid >> 1, kh = (tid & 1) * 64;
    fill_A_row(sw, r, kh, A + (size_t)(rowBase + r) * C + kh, relu);
    int lane = tid & 31, wid = tid >> 5, wm = wid & 1, wn = wid >> 1;
    int g = lane >> 2, t = lane & 3;
    for (int half = 0; half < 2; half++) {
        fill_B(sw, W1 + (size_t)half * 128 * C);
        __syncthreads();
        float acc[4][4][4] = {};
        gemm_tile(sw, acc);
        __syncthreads();
        float* O = half ? Ov : Ou;
#pragma unroll
        for (int mt = 0; mt < 4; mt++) {
            int row = rowBase + wm * 64 + mt * 16 + g;
#pragma unroll
            for (int nt = 0; nt < 4; nt++) {
                int col = wn * 32 + nt * 8 + 2 * t;
                float b0 = half ? 0.f : bias[col];
                float b1 = half ? 0.f : bias[col + 1];
                *(float2*)(O + (size_t)row * C + col) = make_float2(acc[mt][nt][0] + b0, acc[mt][nt][1] + b1);
                *(float2*)(O + (size_t)(row + 8) * C + col) = make_float2(acc[mt][nt][2] + b0, acc[mt][nt][3] + b1);
            }
        }
    }
}

// edge: z = relu(u[d]+v[s]-v[d]); w = z@W2 + b2; atomicMax(>0) into Out[d]
__global__ __launch_bounds__(256, 1) void edge_mma(
    int li, const float* __restrict__ W2, const float* __restrict__ b2,
    const float* __restrict__ U, const float* __restrict__ V, float* __restrict__ Out) {
    int cnt = g_count[li];
    int base = blockIdx.x * 128;
    if (base >= cnt) return;
    extern __shared__ uint32_t sw[];
    __shared__ int2 sd[128];
    __shared__ float bsh[128];
    int tid = threadIdx.x;
    if (tid < 128) {
        int e = base + tid;
        sd[tid] = (e < cnt) ? g_elist[li][e] : make_int2(-1, -1);
        bsh[tid] = b2[tid];
    }
    fill_B(sw, W2);
    __syncthreads();
    int r = tid >> 1, kh = (tid & 1) * 64;
    {
        int2 p = sd[r];
        uint32_t* aH = sw + r * RSW + kh / 2;
        uint32_t* aL = aH + PLANE;
        if (p.y >= 0) {
            const float* u = U + (size_t)p.y * C + kh;
            const float* vs = V + (size_t)p.x * C + kh;
            const float* vd = V + (size_t)p.y * C + kh;
#pragma unroll 4
            for (int k = 0; k < 64; k += 4) {
                float4 a = *(const float4*)(u + k);
                float4 b = *(const float4*)(vs + k);
                float4 c = *(const float4*)(vd + k);
                float z0 = fmaxf(a.x + b.x - c.x, 0.f);
                float z1 = fmaxf(a.y + b.y - c.y, 0.f);
                float z2 = fmaxf(a.z + b.z - c.z, 0.f);
                float z3 = fmaxf(a.w + b.w - c.w, 0.f);
                uint32_t h0, l0, h1, l1;
                split2(z0, z1, h0, l0);
                split2(z2, z3, h1, l1);
                aH[k / 2] = h0; aH[k / 2 + 1] = h1;
                aL[k / 2] = l0; aL[k / 2 + 1] = l1;
            }
        } else {
#pragma unroll 4
            for (int k = 0; k < 64; k += 4) {
                aH[k / 2] = 0; aH[k / 2 + 1] = 0;
                aL[k / 2] = 0; aL[k / 2 + 1] = 0;
            }
        }
    }
    __syncthreads();
    float acc[4][4][4] = {};
    gemm_tile(sw, acc);
    int lane = tid & 31, wid = tid >> 5, wm = wid & 1, wn = wid >> 1;
    int g = lane >> 2, t = lane & 3;
#pragma unroll
    for (int mt = 0; mt < 4; mt++) {
        int rl = wm * 64 + mt * 16 + g;
        int2 q0 = sd[rl];
        int2 q1 = sd[rl + 8];
#pragma unroll
        for (int nt = 0; nt < 4; nt++) {
            int col = wn * 32 + nt * 8 + 2 * t;
            if (q0.y >= 0) {
                unsigned int* orow = (unsigned int*)(Out + (size_t)q0.y * C);
                float v0 = acc[mt][nt][0] + bsh[col];
                float v1 = acc[mt][nt][1] + bsh[col + 1];
                if (v0 > 0.f) atomicMax(orow + col, __float_as_uint(v0));
                if (v1 > 0.f) atomicMax(orow + col + 1, __float_as_uint(v1));
            }
            if (q1.y >= 0) {
                unsigned int* orow = (unsigned int*)(Out + (size_t)q1.y * C);
                float v2 = acc[mt][nt][2] + bsh[col];
                float v3 = acc[mt][nt][3] + bsh[col + 1];
                if (v2 > 0.f) atomicMax(orow + col, __float_as_uint(v2));
                if (v3 > 0.f) atomicMax(orow + col + 1, __float_as_uint(v3));
            }
        }
    }
}

// final: out[r] += relu((s[n]/cnt)@Wl + bl + h[n]@Wr)
__global__ __launch_bounds__(256, 1) void final_mma(
    const float* __restrict__ Wl, const float* __restrict__ bl,
    const float* __restrict__ Wr, int branch, float* __restrict__ out) {
    extern __shared__ uint32_t sw[];
    int rowBase = blockIdx.x * 128;
    int tid = threadIdx.x;
    int r = tid >> 1, kh = (tid & 1) * 64;
    int rr = rowBase + r;
    int n = (rr >> 7) * 384 + (rr & 127);
    float acc[4][4][4] = {};
    // phase 0: A = s[n]*inv, B = Wl
    {
        int cv = g_cnt[branch][n];
        float inv = 1.0f / (float)(cv > 1 ? cv : 1);
        const float* src = g_s + (size_t)n * C + kh;
        uint32_t* aH = sw + r * RSW + kh / 2;
        uint32_t* aL = aH + PLANE;
#pragma unroll 4
        for (int k = 0; k < 64; k += 4) {
            float4 v = *(const float4*)(src + k);
            uint32_t h0, l0, h1, l1;
            split2(v.x * inv, v.y * inv, h0, l0);
            split2(v.z * inv, v.w * inv, h1, l1);
            aH[k / 2] = h0; aH[k / 2 + 1] = h1;
            aL[k / 2] = l0; aL[k / 2 + 1] = l1;
        }
        fill_B(sw, Wl);
    }
    __syncthreads();
    gemm_tile(sw, acc);
    __syncthreads();
    // phase 1: A = h[n], B = Wr (accumulate)
    fill_A_row(sw, r, kh, g_h + (size_t)n * C + kh, 0);
    fill_B(sw, Wr);
    __syncthreads();
    gemm_tile(sw, acc);
    int lane = tid & 31, wid = tid >> 5, wm = wid & 1, wn = wid >> 1;
    int g = lane >> 2, t = lane & 3;
#pragma unroll
    for (int mt = 0; mt < 4; mt++) {
        int row = rowBase + wm * 64 + mt * 16 + g;
#pragma unroll
        for (int nt = 0; nt < 4; nt++) {
            int col = wn * 32 + nt * 8 + 2 * t;
            float2 o0 = *(float2*)(out + (size_t)row * C + col);
            o0.x += fmaxf(acc[mt][nt][0] + bl[col], 0.f);
            o0.y += fmaxf(acc[mt][nt][1] + bl[col + 1], 0.f);
            *(float2*)(out + (size_t)row * C + col) = o0;
            float2 o1 = *(float2*)(out + (size_t)(row + 8) * C + col);
            o1.x += fmaxf(acc[mt][nt][2] + bl[col], 0.f);
            o1.y += fmaxf(acc[mt][nt][3] + bl[col + 1], 0.f);
            *(float2*)(out + (size_t)(row + 8) * C + col) = o1;
        }
    }
}

// ---------------- warp-per-edge aggregations ----------------
__global__ void agg_vpa() {
    int cnt = g_count[0];
    int nw = gridDim.x * (blockDim.x >> 5);
    int w = blockIdx.x * (blockDim.x >> 5) + (threadIdx.x >> 5);
    int lane = threadIdx.x & 31;
    for (int e = w; e < cnt; e += nw) {
        int2 p = g_elist[0][e];
        float4 a = *(const float4*)(g_x + (size_t)p.x * C + lane * 4);
        float4 b = *(const float4*)(g_x + (size_t)p.y * C + lane * 4);
        unsigned int* o = (unsigned int*)(g_xag + (size_t)p.y * C + lane * 4);
        float m;
        m = a.x + b.x; if (m > 0.f) atomicMax(o + 0, __float_as_uint(m));
        m = a.y + b.y; if (m > 0.f) atomicMax(o + 1, __float_as_uint(m));
        m = a.z + b.z; if (m > 0.f) atomicMax(o + 2, __float_as_uint(m));
        m = a.w + b.w; if (m > 0.f) atomicMax(o + 3, __float_as_uint(m));
    }
}
__global__ void ares_k(const float* __restrict__ fcW, const float* __restrict__ fcb) {
    int n = blockIdx.x * (blockDim.x >> 5) + (threadIdx.x >> 5);
    if (n >= NN) return;
    int lane = threadIdx.x & 31;
    float4 a4 = *(const float4*)(g_a + (size_t)n * C + lane * 4);
    float4 w4 = *(const float4*)(fcW + lane * 4);
    float s = a4.x * w4.x + a4.y * w4.y + a4.z * w4.z + a4.w * w4.w;
#pragma unroll
    for (int o = 16; o; o >>= 1) s += __shfl_xor_sync(0xffffffffu, s, o);
    if (lane == 0) g_ares[n] = s + fcb[0];
}
__global__ void agg_acv() {
    int cnt = g_count[2];
    int nw = gridDim.x * (blockDim.x >> 5);
    int w = blockIdx.x * (blockDim.x >> 5) + (threadIdx.x >> 5);
    int lane = threadIdx.x & 31;
    for (int e = w; e < cnt; e += nw) {
        int2 p = g_elist[2][e];
        float wgt = g_ares[p.x];
        float4 a = *(const float4*)(g_x + (size_t)p.x * C + lane * 4);
        float4 b = *(const float4*)(g_x + (size_t)p.y * C + lane * 4);
        float* o = g_xv2 + (size_t)p.y * C + lane * 4;
        atomicAdd(o + 0, wgt * a.x + b.x);
        atomicAdd(o + 1, wgt * a.y + b.y);
        atomicAdd(o + 2, wgt * a.z + b.z);
        atomicAdd(o + 3, wgt * a.w + b.w);
    }
}
__global__ void agg_sage(int li) {
    int cnt = g_count[li];
    int nw = gridDim.x * (blockDim.x >> 5);
    int w = blockIdx.x * (blockDim.x >> 5) + (threadIdx.x >> 5);
    int lane = threadIdx.x & 31;
    for (int e = w; e < cnt; e += nw) {
        int2 p = g_elist[li][e];
        float4 hv = *(const float4*)(g_h + (size_t)p.x * C + lane * 4);
        float* o = g_s + (size_t)p.y * C + lane * 4;
        atomicAdd(o + 0, hv.x);
        atomicAdd(o + 1, hv.y);
        atomicAdd(o + 2, hv.z);
        atomicAdd(o + 3, hv.w);
    }
}

// ---------------- launch ----------------
extern "C" void kernel_launch(void* const* d_in, const int* in_sizes, int n_in,
                              void* d_out, int out_size) {
    (void)in_sizes; (void)n_in; (void)out_size;
    const float* xv = (const float*)d_in[0];
    const float* xa = (const float*)d_in[1];
    const float* W011 = (const float*)d_in[2];
    const float* b011 = (const float*)d_in[3];
    const float* W012 = (const float*)d_in[4];
    const float* b012 = (const float*)d_in[5];
    const float* ecA_W1 = (const float*)d_in[6];
    const float* ecA_b1 = (const float*)d_in[7];
    const float* ecA_W2 = (const float*)d_in[8];
    const float* ecA_b2 = (const float*)d_in[9];
    const float* sage_Wl = (const float*)d_in[22];
    const float* sage_bl = (const float*)d_in[23];
    const float* sage_Wr = (const float*)d_in[24];
    const float* fc_W = (const float*)d_in[25];
    const float* fc_b = (const float*)d_in[26];
    const int* edge_index = (const int*)d_in[27];
    const int* edge_attr = (const int*)d_in[28];
    float* out = (float*)d_out;

    cudaFuncSetAttribute(proj_mma, cudaFuncAttributeMaxDynamicSharedMemorySize, SMEM_BYTES);
    cudaFuncSetAttribute(node_dual_mma, cudaFuncAttributeMaxDynamicSharedMemorySize, SMEM_BYTES);
    cudaFuncSetAttribute(edge_mma, cudaFuncAttributeMaxDynamicSharedMemorySize, SMEM_BYTES);
    cudaFuncSetAttribute(final_mma, cudaFuncAttributeMaxDynamicSharedMemorySize, SMEM_BYTES);

    float *pxag, *pxv2, *pa, *pu, *pv, *ph;
    cudaGetSymbolAddress((void**)&pxag, g_xag);
    cudaGetSymbolAddress((void**)&pxv2, g_xv2);
    cudaGetSymbolAddress((void**)&pa, g_a);
    cudaGetSymbolAddress((void**)&pu, g_u);
    cudaGetSymbolAddress((void**)&pv, g_v);
    cudaGetSymbolAddress((void**)&ph, g_h);

    zero_all<<<8192, 256>>>((float4*)d_out);
    classify_k<<<(EE + 255) / 256, 256>>>(edge_index, edge_attr);
    proj_mma<<<NN / 128, 256, SMEM_BYTES>>>(xv, xa, W011, b011, W012, b012);

    agg_vpa<<<2048, 256>>>();

    node_dual_mma<<<NN / 128, 256, SMEM_BYTES>>>(pxag, ecA_W1, ecA_b1, pu, pv, 0);
    edge_mma<<<2048, 256, SMEM_BYTES>>>(1, ecA_W2, ecA_b2, pu, pv, pa);
    ares_k<<<NN / 8, 256>>>(fc_W, fc_b);

    agg_acv<<<2048, 256>>>();

    for (int k = 0; k < 3; k++) {
        const float* W1 = (const float*)d_in[10 + 4 * k];
        const float* b1 = (const float*)d_in[11 + 4 * k];
        const float* W2 = (const float*)d_in[12 + 4 * k];
        const float* b2 = (const float*)d_in[13 + 4 * k];
        zero_hs<<<8192, 256>>>();
        node_dual_mma<<<NN / 128, 256, SMEM_BYTES>>>(pxv2, W1, b1, pu, pv, 1);
        edge_mma<<<2048, 256, SMEM_BYTES>>>(3 + k, W2, b2, pu, pv, ph);
        agg_sage<<<2048, 256>>>(6 + k);
        final_mma<<<MOUT / 128, 256, SMEM_BYTES>>>(sage_Wl, sage_bl, sage_Wr, k, out);
    }
}

// round 5
// speedup vs baseline: 1.6626x; 1.3025x over previous
#include <cuda_runtime.h>
#include <cuda_bf16.h>
#include <cstdint>

#define NVIS 192
#define NAUD 64
#define TT   128
#define FDIM 1024
#define C    128
#define EE   262144
#define NN   32768
#define NVT  24576
#define MOUT 8192

// smem tile geometry: 4 planes (Ahi, Alo, Bhi, Blo), each 128 rows x 64 bf16x2 words,
// row stride 68 words (272B) -> conflict-free fragment loads (17*16B).
#define RSW   68
#define PLANE (128 * RSW)          // words per plane
#define SMEM_BYTES (4 * PLANE * 4) // 139264

// ---------------- helpers ----------------
__device__ __forceinline__ void split2(float x, float y, uint32_t& hi, uint32_t& lo) {
    __nv_bfloat16 hx = __float2bfloat16(x), hy = __float2bfloat16(y);
    __nv_bfloat16 lx = __float2bfloat16(x - __bfloat162float(hx));
    __nv_bfloat16 ly = __float2bfloat16(y - __bfloat162float(hy));
    hi = (uint32_t)*(uint16_t*)&hx | ((uint32_t)*(uint16_t*)&hy << 16);
    lo = (uint32_t)*(uint16_t*)&lx | ((uint32_t)*(uint16_t*)&ly << 16);
}

__device__ __forceinline__ void mma_bf16(float* c, const uint32_t* a, uint32_t b0, uint32_t b1) {
    asm volatile(
        "mma.sync.aligned.m16n8k16.row.col.f32.bf16.bf16.f32 "
        "{%0,%1,%2,%3}, {%4,%5,%6,%7}, {%8,%9}, {%0,%1,%2,%3};"
        : "+f"(c[0]), "+f"(c[1]), "+f"(c[2]), "+f"(c[3])
        : "r"(a[0]), "r"(a[1]), "r"(a[2]), "r"(a[3]), "r"(b0), "r"(b1));
}

#define LDSM_X4(r, a) \
    asm volatile("ldmatrix.sync.aligned.m8n8.x4.shared.b16 {%0,%1,%2,%3}, [%4];" \
        : "=r"((r)[0]), "=r"((r)[1]), "=r"((r)[2]), "=r"((r)[3]) : "r"(a))
#define LDSM_X2(r, a) \
    asm volatile("ldmatrix.sync.aligned.m8n8.x2.shared.b16 {%0,%1}, [%2];" \
        : "=r"((r)[0]), "=r"((r)[1]) : "r"(a))

__device__ __forceinline__ uint32_t s2u(const void* p) {
    unsigned long long x;
    asm("cvta.to.shared.u64 %0, %1;" : "=l"(x) : "l"(p));
    return (uint32_t)x;
}

// 128x128x128 tile GEMM: acc += A @ B^T, 3-pass bf16 split, ldmatrix fragment feed.
__device__ __forceinline__ void gemm_tile(const uint32_t* sw, float acc[4][4][4]) {
    int lane = threadIdx.x & 31, wid = threadIdx.x >> 5;
    int wm = wid & 1, wn = wid >> 1;   // warp grid 2(m) x 4(n)
    uint32_t swb = s2u(sw);
    int ar = wm * 64 + (lane & 15);
    int ac = (lane >> 4) * 4;
    uint32_t aH = swb + (uint32_t)((ar * RSW + ac) << 2);
    uint32_t aL = aH + PLANE * 4;
    int br = wn * 32 + (lane & 7);
    int bc = ((lane >> 3) & 1) * 4;
    uint32_t bH = swb + 2u * PLANE * 4 + (uint32_t)((br * RSW + bc) << 2);
    uint32_t bL = bH + PLANE * 4;
#pragma unroll
    for (int ks = 0; ks < 8; ks++) {
        uint32_t kb = (uint32_t)(ks * 8 * 4);
        uint32_t bh[4][2], bl[4][2];
#pragma unroll
        for (int nt = 0; nt < 4; nt++) {
            LDSM_X2(bh[nt], bH + (uint32_t)(nt * 8 * RSW * 4) + kb);
            LDSM_X2(bl[nt], bL + (uint32_t)(nt * 8 * RSW * 4) + kb);
        }
#pragma unroll
        for (int mt = 0; mt < 4; mt++) {
            uint32_t ah[4], al[4];
            LDSM_X4(ah, aH + (uint32_t)(mt * 16 * RSW * 4) + kb);
            LDSM_X4(al, aL + (uint32_t)(mt * 16 * RSW * 4) + kb);
#pragma unroll
            for (int nt = 0; nt < 4; nt++) {
                mma_bf16(acc[mt][nt], ah, bh[nt][0], bh[nt][1]);
                mma_bf16(acc[mt][nt], ah, bl[nt][0], bl[nt][1]);
                mma_bf16(acc[mt][nt], al, bh[nt][0], bh[nt][1]);
            }
        }
    }
}

// ---------------- presplit weights (filled once per launch) ----------------
// layout: g_wsplit[mat][plane(0=hi,1=lo)][n][kpair]
__device__ uint32_t g_wsplit[30][2][128][64];

struct WPtrs { const float* p[12]; };

// one block per matrix; stage W[128][128] in smem, transpose+split out
__global__ __launch_bounds__(256) void prep_w(WPtrs P) {
    extern __shared__ float st[];  // [128][132]
    int m = blockIdx.x, tid = threadIdx.x;
    const float* W;
    if (m < 8)       W = P.p[0] + (size_t)m * 128 * C;
    else if (m < 16) W = P.p[1] + (size_t)(m - 8) * 128 * C;
    else {
        int r = m - 16;
        if (r < 12) {
            int cvi = r / 3, w = r % 3;
            const float* W1 = P.p[2 + 2 * cvi];
            const float* W2 = P.p[3 + 2 * cvi];
            W = (w < 2) ? (W1 + (size_t)w * 128 * C) : W2;
        } else W = (r == 12) ? P.p[10] : P.p[11];
    }
    for (int i = tid; i < 128 * 32; i += 256) {
        int row = i >> 5, c4 = i & 31;
        float4 v = *(const float4*)(W + (size_t)row * C + c4 * 4);
        st[row * 132 + c4 * 4 + 0] = v.x;
        st[row * 132 + c4 * 4 + 1] = v.y;
        st[row * 132 + c4 * 4 + 2] = v.z;
        st[row * 132 + c4 * 4 + 3] = v.w;
    }
    __syncthreads();
    for (int i = tid; i < 128 * 64; i += 256) {
        int n = i >> 6, j = i & 63;
        uint32_t h, l;
        split2(st[(2 * j) * 132 + n], st[(2 * j + 1) * 132 + n], h, l);
        g_wsplit[m][0][n][j] = h;
        g_wsplit[m][1][n][j] = l;
    }
}

// copy presplit B planes into smem (hi->plane2, lo->plane3)
__device__ __forceinline__ void fill_B_copy(uint32_t* sw, int mat) {
    const float4* src = (const float4*)g_wsplit[mat];
    int tid = threadIdx.x;
#pragma unroll
    for (int it = 0; it < 16; it++) {
        int idx = tid + it * 256;        // over [2][128][16] float4 units
        int pl = idx >> 11, rem = idx & 2047;
        int n = rem >> 4, f = rem & 15;
        *(float4*)&sw[(2 + pl) * PLANE + n * RSW + f * 4] = src[idx];
    }
}

// fill one 64-k half of A row r from src (with optional relu)
__device__ __forceinline__ void fill_A_row(uint32_t* sw, int r, int kh,
                                           const float* __restrict__ src, int relu) {
    uint32_t* aH = sw + r * RSW + kh / 2;
    uint32_t* aL = aH + PLANE;
#pragma unroll 4
    for (int k = 0; k < 64; k += 4) {
        float4 v = *(const float4*)(src + k);
        if (relu) { v.x = fmaxf(v.x, 0.f); v.y = fmaxf(v.y, 0.f); v.z = fmaxf(v.z, 0.f); v.w = fmaxf(v.w, 0.f); }
        uint32_t h0, l0, h1, l1;
        split2(v.x, v.y, h0, l0);
        split2(v.z, v.w, h1, l1);
        aH[k / 2] = h0; aH[k / 2 + 1] = h1;
        aL[k / 2] = l0; aL[k / 2 + 1] = l1;
    }
}

// ---------------- device scratch ----------------
__device__ float g_x[NN * C];
__device__ float g_xag[NN * C];
__device__ float g_a[NN * C];
__device__ float g_ares[NN];
__device__ float g_xv2[NN * C];
__device__ float g_u[NN * C];
__device__ float g_v[NN * C];
__device__ float g_h[NN * C];
__device__ float g_s[NN * C];
__device__ int   g_cnt[3][NN];
__device__ int2  g_elist[9][EE];
__device__ int   g_count[9];

// ---------------- zero / classify ----------------
__global__ void zero_all(float4* out4) {
    const long A4 = (long)NN * C / 4;
    const long O4 = (long)MOUT * C / 4;
    const long C4 = 3L * NN / 4;
    const long total = 3 * A4 + O4 + C4;
    float4 z = make_float4(0.f, 0.f, 0.f, 0.f);
    for (long i = blockIdx.x * (long)blockDim.x + threadIdx.x; i < total;
         i += (long)gridDim.x * blockDim.x) {
        if (i < A4)               ((float4*)g_xag)[i] = z;
        else if (i < 2 * A4)      ((float4*)g_a)[i - A4] = z;
        else if (i < 3 * A4)      ((float4*)g_xv2)[i - 2 * A4] = z;
        else if (i < 3 * A4 + O4) out4[i - 3 * A4] = z;
        else                      ((float4*)g_cnt)[i - 3 * A4 - O4] = z;
    }
    if (blockIdx.x == 0 && threadIdx.x < 9) g_count[threadIdx.x] = 0;
}
__global__ void zero_hs() {
    const long A4 = (long)NN * C / 4;
    float4 z = make_float4(0.f, 0.f, 0.f, 0.f);
    for (long i = blockIdx.x * (long)blockDim.x + threadIdx.x; i < 2 * A4;
         i += (long)gridDim.x * blockDim.x) {
        if (i < A4) ((float4*)g_h)[i] = z;
        else        ((float4*)g_s)[i - A4] = z;
    }
}
__global__ void classify_k(const int* __restrict__ ei, const int* __restrict__ attr) {
    int e = blockIdx.x * blockDim.x + threadIdx.x;
    if (e >= EE) return;
    int a = attr[e];
    int2 p = make_int2(ei[e], ei[EE + e]);
    if (a == -3) { int i = atomicAdd(&g_count[0], 1); g_elist[0][i] = p; }
    if (a == -2) { int i = atomicAdd(&g_count[1], 1); g_elist[1][i] = p; }
    if (a == 3)  { int i = atomicAdd(&g_count[2], 1); g_elist[2][i] = p; }
    bool m1 = (a >= 0) && (a <= 1);
    bool m2 = (a >= -1) && (a <= 0);
    bool m3 = (a >= -1) && (a <= 1);
    bool dout = (p.y < NVT) && (((p.y >> 7) % 3) == 0);
    if (m1) { int i = atomicAdd(&g_count[3], 1); g_elist[3][i] = p; atomicAdd(&g_cnt[0][p.y], 1);
              if (dout) { int j = atomicAdd(&g_count[6], 1); g_elist[6][j] = p; } }
    if (m2) { int i = atomicAdd(&g_count[4], 1); g_elist[4][i] = p; atomicAdd(&g_cnt[1][p.y], 1);
              if (dout) { int j = atomicAdd(&g_count[7], 1); g_elist[7][j] = p; } }
    if (m3) { int i = atomicAdd(&g_count[5], 1); g_elist[5][i] = p; atomicAdd(&g_cnt[2][p.y], 1);
              if (dout) { int j = atomicAdd(&g_count[8], 1); g_elist[8][j] = p; } }
}

// ---------------- mma GEMM kernels ----------------

// proj: g_x = [xv;xa] @ W + b   (K=1024, 8 presplit chunk-mats)
__global__ __launch_bounds__(256, 1) void proj_mma(
    const float* __restrict__ xv, const float* __restrict__ xa,
    const float* __restrict__ bv, const float* __restrict__ ba) {
    extern __shared__ uint32_t sw[];
    int rowBase = blockIdx.x * 128;
    bool vis = rowBase < NVT;
    const float* X = vis ? (xv + (size_t)rowBase * FDIM) : (xa + (size_t)(rowBase - NVT) * FDIM);
    const float* bias = vis ? bv : ba;
    int matBase = vis ? 0 : 8;
    int tid = threadIdx.x;
    int r = tid >> 1, kh = (tid & 1) * 64;
    float acc[4][4][4] = {};
    for (int chunk = 0; chunk < 8; chunk++) {
        fill_A_row(sw, r, kh, X + (size_t)r * FDIM + chunk * 128 + kh, 0);
        fill_B_copy(sw, matBase + chunk);
        __syncthreads();
        gemm_tile(sw, acc);
        __syncthreads();
    }
    int lane = tid & 31, wid = tid >> 5, wm = wid & 1, wn = wid >> 1;
    int g = lane >> 2, t = lane & 3;
#pragma unroll
    for (int mt = 0; mt < 4; mt++) {
        int row = rowBase + wm * 64 + mt * 16 + g;
#pragma unroll
        for (int nt = 0; nt < 4; nt++) {
            int col = wn * 32 + nt * 8 + 2 * t;
            *(float2*)(g_x + (size_t)row * C + col) =
                make_float2(acc[mt][nt][0] + bias[col], acc[mt][nt][1] + bias[col + 1]);
            *(float2*)(g_x + (size_t)(row + 8) * C + col) =
                make_float2(acc[mt][nt][2] + bias[col], acc[mt][nt][3] + bias[col + 1]);
        }
    }
}

// node dual: Ou = act(A)@W1h0 + bias, Ov = act(A)@W1h1
__global__ __launch_bounds__(256, 1) void node_dual_mma(
    const float* __restrict__ A, int mat0,
    const float* __restrict__ bias, float* __restrict__ Ou, float* __restrict__ Ov, int relu) {
    extern __shared__ uint32_t sw[];
    int rowBase = blockIdx.x * 128;
    int tid = threadIdx.x;
    int r = tid >> 1, kh = (tid & 1) * 64;
    fill_A_row(sw, r, kh, A + (size_t)(rowBase + r) * C + kh, relu);
    int lane = tid & 31, wid = tid >> 5, wm = wid & 1, wn = wid >> 1;
    int g = lane >> 2, t = lane & 3;
    for (int half = 0; half < 2; half++) {
        fill_B_copy(sw, mat0 + half);
        __syncthreads();
        float acc[4][4][4] = {};
        gemm_tile(sw, acc);
        __syncthreads();
        float* O = half ? Ov : Ou;
#pragma unroll
        for (int mt = 0; mt < 4; mt++) {
            int row = rowBase + wm * 64 + mt * 16 + g;
#pragma unroll
            for (int nt = 0; nt < 4; nt++) {
                int col = wn * 32 + nt * 8 + 2 * t;
                float b0 = half ? 0.f : bias[col];
                float b1 = half ? 0.f : bias[col + 1];
                *(float2*)(O + (size_t)row * C + col) = make_float2(acc[mt][nt][0] + b0, acc[mt][nt][1] + b1);
                *(float2*)(O + (size_t)(row + 8) * C + col) = make_float2(acc[mt][nt][2] + b0, acc[mt][nt][3] + b1);
            }
        }
    }
}

// edge: z = relu(u[d]+v[s]-v[d]); w = z@W2 + b2; atomicMax(>0) into Out[d]
__global__ __launch_bounds__(256, 1) void edge_mma(
    int li, int mat, const float* __restrict__ b2,
    const float* __restrict__ U, const float* __restrict__ V, float* __restrict__ Out) {
    int cnt = g_count[li];
    int base = blockIdx.x * 128;
    if (base >= cnt) return;
    extern __shared__ uint32_t sw[];
    __shared__ int2 sd[128];
    __shared__ float bsh[128];
    int tid = threadIdx.x;
    if (tid < 128) {
        int e = base + tid;
        sd[tid] = (e < cnt) ? g_elist[li][e] : make_int2(-1, -1);
        bsh[tid] = b2[tid];
    }
    fill_B_copy(sw, mat);
    __syncthreads();
    int r = tid >> 1, kh = (tid & 1) * 64;
    {
        int2 p = sd[r];
        uint32_t* aH = sw + r * RSW + kh / 2;
        uint32_t* aL = aH + PLANE;
        if (p.y >= 0) {
            const float* u = U + (size_t)p.y * C + kh;
            const float* vs = V + (size_t)p.x * C + kh;
            const float* vd = V + (size_t)p.y * C + kh;
#pragma unroll 4
            for (int k = 0; k < 64; k += 4) {
                float4 a = *(const float4*)(u + k);
                float4 b = *(const float4*)(vs + k);
                float4 c = *(const float4*)(vd + k);
                float z0 = fmaxf(a.x + b.x - c.x, 0.f);
                float z1 = fmaxf(a.y + b.y - c.y, 0.f);
                float z2 = fmaxf(a.z + b.z - c.z, 0.f);
                float z3 = fmaxf(a.w + b.w - c.w, 0.f);
                uint32_t h0, l0, h1, l1;
                split2(z0, z1, h0, l0);
                split2(z2, z3, h1, l1);
                aH[k / 2] = h0; aH[k / 2 + 1] = h1;
                aL[k / 2] = l0; aL[k / 2 + 1] = l1;
            }
        } else {
#pragma unroll 4
            for (int k = 0; k < 64; k += 4) {
                aH[k / 2] = 0; aH[k / 2 + 1] = 0;
                aL[k / 2] = 0; aL[k / 2 + 1] = 0;
            }
        }
    }
    __syncthreads();
    float acc[4][4][4] = {};
    gemm_tile(sw, acc);
    int lane = tid & 31, wid = tid >> 5, wm = wid & 1, wn = wid >> 1;
    int g = lane >> 2, t = lane & 3;
#pragma unroll
    for (int mt = 0; mt < 4; mt++) {
        int rl = wm * 64 + mt * 16 + g;
        int2 q0 = sd[rl];
        int2 q1 = sd[rl + 8];
#pragma unroll
        for (int nt = 0; nt < 4; nt++) {
            int col = wn * 32 + nt * 8 + 2 * t;
            if (q0.y >= 0) {
                unsigned int* orow = (unsigned int*)(Out + (size_t)q0.y * C);
                float v0 = acc[mt][nt][0] + bsh[col];
                float v1 = acc[mt][nt][1] + bsh[col + 1];
                if (v0 > 0.f) atomicMax(orow + col, __float_as_uint(v0));
                if (v1 > 0.f) atomicMax(orow + col + 1, __float_as_uint(v1));
            }
            if (q1.y >= 0) {
                unsigned int* orow = (unsigned int*)(Out + (size_t)q1.y * C);
                float v2 = acc[mt][nt][2] + bsh[col];
                float v3 = acc[mt][nt][3] + bsh[col + 1];
                if (v2 > 0.f) atomicMax(orow + col, __float_as_uint(v2));
                if (v3 > 0.f) atomicMax(orow + col + 1, __float_as_uint(v3));
            }
        }
    }
}

// final: out[r] += relu((s[n]/cnt)@Wl + bl + h[n]@Wr)
__global__ __launch_bounds__(256, 1) void final_mma(
    const float* __restrict__ bl, int branch, float* __restrict__ out) {
    extern __shared__ uint32_t sw[];
    int rowBase = blockIdx.x * 128;
    int tid = threadIdx.x;
    int r = tid >> 1, kh = (tid & 1) * 64;
    int rr = rowBase + r;
    int n = (rr >> 7) * 384 + (rr & 127);
    float acc[4][4][4] = {};
    {
        int cv = g_cnt[branch][n];
        float inv = 1.0f / (float)(cv > 1 ? cv : 1);
        const float* src = g_s + (size_t)n * C + kh;
        uint32_t* aH = sw + r * RSW + kh / 2;
        uint32_t* aL = aH + PLANE;
#pragma unroll 4
        for (int k = 0; k < 64; k += 4) {
            float4 v = *(const float4*)(src + k);
            uint32_t h0, l0, h1, l1;
            split2(v.x * inv, v.y * inv, h0, l0);
            split2(v.z * inv, v.w * inv, h1, l1);
            aH[k / 2] = h0; aH[k / 2 + 1] = h1;
            aL[k / 2] = l0; aL[k / 2 + 1] = l1;
        }
        fill_B_copy(sw, 28);
    }
    __syncthreads();
    gemm_tile(sw, acc);
    __syncthreads();
    fill_A_row(sw, r, kh, g_h + (size_t)n * C + kh, 0);
    fill_B_copy(sw, 29);
    __syncthreads();
    gemm_tile(sw, acc);
    int lane = tid & 31, wid = tid >> 5, wm = wid & 1, wn = wid >> 1;
    int g = lane >> 2, t = lane & 3;
#pragma unroll
    for (int mt = 0; mt < 4; mt++) {
        int row = rowBase + wm * 64 + mt * 16 + g;
#pragma unroll
        for (int nt = 0; nt < 4; nt++) {
            int col = wn * 32 + nt * 8 + 2 * t;
            float2 o0 = *(float2*)(out + (size_t)row * C + col);
            o0.x += fmaxf(acc[mt][nt][0] + bl[col], 0.f);
            o0.y += fmaxf(acc[mt][nt][1] + bl[col + 1], 0.f);
            *(float2*)(out + (size_t)row * C + col) = o0;
            float2 o1 = *(float2*)(out + (size_t)(row + 8) * C + col);
            o1.x += fmaxf(acc[mt][nt][2] + bl[col], 0.f);
            o1.y += fmaxf(acc[mt][nt][3] + bl[col + 1], 0.f);
            *(float2*)(out + (size_t)(row + 8) * C + col) = o1;
        }
    }
}

// ---------------- warp-per-edge aggregations ----------------
__global__ void agg_vpa() {
    int cnt = g_count[0];
    int nw = gridDim.x * (blockDim.x >> 5);
    int w = blockIdx.x * (blockDim.x >> 5) + (threadIdx.x >> 5);
    int lane = threadIdx.x & 31;
    for (int e = w; e < cnt; e += nw) {
        int2 p = g_elist[0][e];
        float4 a = *(const float4*)(g_x + (size_t)p.x * C + lane * 4);
        float4 b = *(const float4*)(g_x + (size_t)p.y * C + lane * 4);
        unsigned int* o = (unsigned int*)(g_xag + (size_t)p.y * C + lane * 4);
        float m;
        m = a.x + b.x; if (m > 0.f) atomicMax(o + 0, __float_as_uint(m));
        m = a.y + b.y; if (m > 0.f) atomicMax(o + 1, __float_as_uint(m));
        m = a.z + b.z; if (m > 0.f) atomicMax(o + 2, __float_as_uint(m));
        m = a.w + b.w; if (m > 0.f) atomicMax(o + 3, __float_as_uint(m));
    }
}
__global__ void ares_k(const float* __restrict__ fcW, const float* __restrict__ fcb) {
    int n = blockIdx.x * (blockDim.x >> 5) + (threadIdx.x >> 5);
    if (n >= NN) return;
    int lane = threadIdx.x & 31;
    float4 a4 = *(const float4*)(g_a + (size_t)n * C + lane * 4);
    float4 w4 = *(const float4*)(fcW + lane * 4);
    float s = a4.x * w4.x + a4.y * w4.y + a4.z * w4.z + a4.w * w4.w;
#pragma unroll
    for (int o = 16; o; o >>= 1) s += __shfl_xor_sync(0xffffffffu, s, o);
    if (lane == 0) g_ares[n] = s + fcb[0];
}
__global__ void agg_acv() {
    int cnt = g_count[2];
    int nw = gridDim.x * (blockDim.x >> 5);
    int w = blockIdx.x * (blockDim.x >> 5) + (threadIdx.x >> 5);
    int lane = threadIdx.x & 31;
    for (int e = w; e < cnt; e += nw) {
        int2 p = g_elist[2][e];
        float wgt = g_ares[p.x];
        float4 a = *(const float4*)(g_x + (size_t)p.x * C + lane * 4);
        float4 b = *(const float4*)(g_x + (size_t)p.y * C + lane * 4);
        float* o = g_xv2 + (size_t)p.y * C + lane * 4;
        atomicAdd(o + 0, wgt * a.x + b.x);
        atomicAdd(o + 1, wgt * a.y + b.y);
        atomicAdd(o + 2, wgt * a.z + b.z);
        atomicAdd(o + 3, wgt * a.w + b.w);
    }
}
__global__ void agg_sage(int li) {
    int cnt = g_count[li];
    int nw = gridDim.x * (blockDim.x >> 5);
    int w = blockIdx.x * (blockDim.x >> 5) + (threadIdx.x >> 5);
    int lane = threadIdx.x & 31;
    for (int e = w; e < cnt; e += nw) {
        int2 p = g_elist[li][e];
        float4 hv = *(const float4*)(g_h + (size_t)p.x * C + lane * 4);
        float* o = g_s + (size_t)p.y * C + lane * 4;
        atomicAdd(o + 0, hv.x);
        atomicAdd(o + 1, hv.y);
        atomicAdd(o + 2, hv.z);
        atomicAdd(o + 3, hv.w);
    }
}

// ---------------- launch ----------------
extern "C" void kernel_launch(void* const* d_in, const int* in_sizes, int n_in,
                              void* d_out, int out_size) {
    (void)in_sizes; (void)n_in; (void)out_size;
    const float* xv = (const float*)d_in[0];
    const float* xa = (const float*)d_in[1];
    const float* b011 = (const float*)d_in[3];
    const float* b012 = (const float*)d_in[5];
    const float* ecA_b1 = (const float*)d_in[7];
    const float* ecA_b2 = (const float*)d_in[9];
    const float* sage_bl = (const float*)d_in[23];
    const float* fc_W = (const float*)d_in[25];
    const float* fc_b = (const float*)d_in[26];
    const int* edge_index = (const int*)d_in[27];
    const int* edge_attr = (const int*)d_in[28];
    float* out = (float*)d_out;

    WPtrs P;
    P.p[0] = (const float*)d_in[2];   // W011
    P.p[1] = (const float*)d_in[4];   // W012
    P.p[2] = (const float*)d_in[6];   // ecA_W1
    P.p[3] = (const float*)d_in[8];   // ecA_W2
    P.p[4] = (const float*)d_in[10];  // ec1_W1
    P.p[5] = (const float*)d_in[12];  // ec1_W2
    P.p[6] = (const float*)d_in[14];  // ec2_W1
    P.p[7] = (const float*)d_in[16];  // ec2_W2
    P.p[8] = (const float*)d_in[18];  // ec3_W1
    P.p[9] = (const float*)d_in[20];  // ec3_W2
    P.p[10] = (const float*)d_in[22]; // sage_Wl
    P.p[11] = (const float*)d_in[24]; // sage_Wr

    cudaFuncSetAttribute(prep_w, cudaFuncAttributeMaxDynamicSharedMemorySize, 128 * 132 * 4);
    cudaFuncSetAttribute(proj_mma, cudaFuncAttributeMaxDynamicSharedMemorySize, SMEM_BYTES);
    cudaFuncSetAttribute(node_dual_mma, cudaFuncAttributeMaxDynamicSharedMemorySize, SMEM_BYTES);
    cudaFuncSetAttribute(edge_mma, cudaFuncAttributeMaxDynamicSharedMemorySize, SMEM_BYTES);
    cudaFuncSetAttribute(final_mma, cudaFuncAttributeMaxDynamicSharedMemorySize, SMEM_BYTES);

    float *pxag, *pxv2, *pa, *pu, *pv, *ph;
    cudaGetSymbolAddress((void**)&pxag, g_xag);
    cudaGetSymbolAddress((void**)&pxv2, g_xv2);
    cudaGetSymbolAddress((void**)&pa, g_a);
    cudaGetSymbolAddress((void**)&pu, g_u);
    cudaGetSymbolAddress((void**)&pv, g_v);
    cudaGetSymbolAddress((void**)&ph, g_h);

    zero_all<<<8192, 256>>>((float4*)d_out);
    prep_w<<<30, 256, 128 * 132 * 4>>>(P);
    classify_k<<<(EE + 255) / 256, 256>>>(edge_index, edge_attr);
    proj_mma<<<NN / 128, 256, SMEM_BYTES>>>(xv, xa, b011, b012);

    agg_vpa<<<2048, 256>>>();

    node_dual_mma<<<NN / 128, 256, SMEM_BYTES>>>(pxag, 16, ecA_b1, pu, pv, 0);
    edge_mma<<<2048, 256, SMEM_BYTES>>>(1, 18, ecA_b2, pu, pv, pa);
    ares_k<<<NN / 8, 256>>>(fc_W, fc_b);

    agg_acv<<<2048, 256>>>();

    for (int k = 0; k < 3; k++) {
        const float* b1 = (const float*)d_in[11 + 4 * k];
        const float* b2 = (const float*)d_in[13 + 4 * k];
        zero_hs<<<8192, 256>>>();
        node_dual_mma<<<NN / 128, 256, SMEM_BYTES>>>(pxv2, 19 + 3 * k, b1, pu, pv, 1);
        edge_mma<<<2048, 256, SMEM_BYTES>>>(3 + k, 21 + 3 * k, b2, pu, pv, ph);
        agg_sage<<<2048, 256>>>(6 + k);
        final_mma<<<MOUT / 128, 256, SMEM_BYTES>>>(sage_bl, k, out);
    }
}

// round 6
// speedup vs baseline: 1.7353x; 1.0437x over previous
#include <cuda_runtime.h>
#include <cuda_bf16.h>
#include <cstdint>

#define NVIS 192
#define NAUD 64
#define TT   128
#define FDIM 1024
#define C    128
#define EE   262144
#define NN   32768
#define NVT  24576
#define MOUT 8192

// BK=64 tile: 4 planes (Ahi, Alo, Bhi, Blo), each 128 rows x 32 bf16x2 words,
// row stride 36 words (144B = 9*16B) -> conflict-free, 16B-aligned ldmatrix rows.
#define RSW   36
#define PLANE (128 * RSW)          // 4608 words per plane
#define SMEM_BYTES (4 * PLANE * 4) // 73728 -> 2 CTAs/SM

// ---------------- helpers ----------------
__device__ __forceinline__ void split2(float x, float y, uint32_t& hi, uint32_t& lo) {
    __nv_bfloat16 hx = __float2bfloat16(x), hy = __float2bfloat16(y);
    __nv_bfloat16 lx = __float2bfloat16(x - __bfloat162float(hx));
    __nv_bfloat16 ly = __float2bfloat16(y - __bfloat162float(hy));
    hi = (uint32_t)*(uint16_t*)&hx | ((uint32_t)*(uint16_t*)&hy << 16);
    lo = (uint32_t)*(uint16_t*)&lx | ((uint32_t)*(uint16_t*)&ly << 16);
}

__device__ __forceinline__ void mma_bf16(float* c, const uint32_t* a, uint32_t b0, uint32_t b1) {
    asm volatile(
        "mma.sync.aligned.m16n8k16.row.col.f32.bf16.bf16.f32 "
        "{%0,%1,%2,%3}, {%4,%5,%6,%7}, {%8,%9}, {%0,%1,%2,%3};"
        : "+f"(c[0]), "+f"(c[1]), "+f"(c[2]), "+f"(c[3])
        : "r"(a[0]), "r"(a[1]), "r"(a[2]), "r"(a[3]), "r"(b0), "r"(b1));
}

#define LDSM_X4(r, a) \
    asm volatile("ldmatrix.sync.aligned.m8n8.x4.shared.b16 {%0,%1,%2,%3}, [%4];" \
        : "=r"((r)[0]), "=r"((r)[1]), "=r"((r)[2]), "=r"((r)[3]) : "r"(a))
#define LDSM_X2(r, a) \
    asm volatile("ldmatrix.sync.aligned.m8n8.x2.shared.b16 {%0,%1}, [%2];" \
        : "=r"((r)[0]), "=r"((r)[1]) : "r"(a))

__device__ __forceinline__ uint32_t s2u(const void* p) {
    unsigned long long x;
    asm("cvta.to.shared.u64 %0, %1;" : "=l"(x) : "l"(p));
    return (uint32_t)x;
}

// 128x128x64 tile GEMM: acc += A @ B^T, 3-pass bf16 split, ldmatrix feed.
__device__ __forceinline__ void gemm_tile64(const uint32_t* sw, float acc[4][4][4]) {
    int lane = threadIdx.x & 31, wid = threadIdx.x >> 5;
    int wm = wid & 1, wn = wid >> 1;   // warp grid 2(m) x 4(n)
    uint32_t swb = s2u(sw);
    int ar = wm * 64 + (lane & 15);
    int ac = (lane >> 4) * 4;
    uint32_t aH = swb + (uint32_t)((ar * RSW + ac) << 2);
    uint32_t aL = aH + PLANE * 4;
    int br = wn * 32 + (lane & 7);
    int bc = ((lane >> 3) & 1) * 4;
    uint32_t bH = swb + 2u * PLANE * 4 + (uint32_t)((br * RSW + bc) << 2);
    uint32_t bL = bH + PLANE * 4;
#pragma unroll
    for (int ks = 0; ks < 4; ks++) {
        uint32_t kb = (uint32_t)(ks * 8 * 4);
        uint32_t bh[4][2], bl[4][2];
#pragma unroll
        for (int nt = 0; nt < 4; nt++) {
            LDSM_X2(bh[nt], bH + (uint32_t)(nt * 8 * RSW * 4) + kb);
            LDSM_X2(bl[nt], bL + (uint32_t)(nt * 8 * RSW * 4) + kb);
        }
#pragma unroll
        for (int mt = 0; mt < 4; mt++) {
            uint32_t ah[4], al[4];
            LDSM_X4(ah, aH + (uint32_t)(mt * 16 * RSW * 4) + kb);
            LDSM_X4(al, aL + (uint32_t)(mt * 16 * RSW * 4) + kb);
#pragma unroll
            for (int nt = 0; nt < 4; nt++) {
                mma_bf16(acc[mt][nt], ah, bh[nt][0], bh[nt][1]);
                mma_bf16(acc[mt][nt], ah, bl[nt][0], bl[nt][1]);
                mma_bf16(acc[mt][nt], al, bh[nt][0], bh[nt][1]);
            }
        }
    }
}

// ---------------- presplit weights ----------------
// g_wsplit[mat][plane(0=hi,1=lo)][n][kpair 0..63]
__device__ uint32_t g_wsplit[30][2][128][64];

struct WPtrs { const float* p[12]; };

__global__ __launch_bounds__(256) void prep_w(WPtrs P) {
    extern __shared__ float st[];  // [128][132]
    int m = blockIdx.x, tid = threadIdx.x;
    const float* W;
    if (m < 8)       W = P.p[0] + (size_t)m * 128 * C;
    else if (m < 16) W = P.p[1] + (size_t)(m - 8) * 128 * C;
    else {
        int r = m - 16;
        if (r < 12) {
            int cvi = r / 3, w = r % 3;
            const float* W1 = P.p[2 + 2 * cvi];
            const float* W2 = P.p[3 + 2 * cvi];
            W = (w < 2) ? (W1 + (size_t)w * 128 * C) : W2;
        } else W = (r == 12) ? P.p[10] : P.p[11];
    }
    for (int i = tid; i < 128 * 32; i += 256) {
        int row = i >> 5, c4 = i & 31;
        float4 v = *(const float4*)(W + (size_t)row * C + c4 * 4);
        st[row * 132 + c4 * 4 + 0] = v.x;
        st[row * 132 + c4 * 4 + 1] = v.y;
        st[row * 132 + c4 * 4 + 2] = v.z;
        st[row * 132 + c4 * 4 + 3] = v.w;
    }
    __syncthreads();
    for (int i = tid; i < 128 * 64; i += 256) {
        int n = i >> 6, j = i & 63;
        uint32_t h, l;
        split2(st[(2 * j) * 132 + n], st[(2 * j + 1) * 132 + n], h, l);
        g_wsplit[m][0][n][j] = h;
        g_wsplit[m][1][n][j] = l;
    }
}

// copy one K-half (32 kpairs) of presplit B planes into smem
__device__ __forceinline__ void fill_B64(uint32_t* sw, int mat, int half) {
    int tid = threadIdx.x;
#pragma unroll
    for (int it = 0; it < 8; it++) {
        int idx = tid + it * 256;          // over [2][128][8] float4 units
        int pl = idx >> 10, rem = idx & 1023;
        int n = rem >> 3, f = rem & 7;
        float4 v = *(const float4*)&g_wsplit[mat][pl][n][half * 32 + f * 4];
        *(float4*)&sw[(2 + pl) * PLANE + n * RSW + f * 4] = v;
    }
}

// fill 32 k-values of A row r (quarter q: k offset q*32 within the 64-k tile)
__device__ __forceinline__ void fill_A64(uint32_t* sw, int r, int q,
                                         const float* __restrict__ src, int relu) {
    uint32_t* aH = sw + r * RSW + q * 16;
    uint32_t* aL = aH + PLANE;
#pragma unroll 2
    for (int k = 0; k < 32; k += 4) {
        float4 v = *(const float4*)(src + k);
        if (relu) { v.x = fmaxf(v.x, 0.f); v.y = fmaxf(v.y, 0.f); v.z = fmaxf(v.z, 0.f); v.w = fmaxf(v.w, 0.f); }
        uint32_t h0, l0, h1, l1;
        split2(v.x, v.y, h0, l0);
        split2(v.z, v.w, h1, l1);
        aH[k / 2] = h0; aH[k / 2 + 1] = h1;
        aL[k / 2] = l0; aL[k / 2 + 1] = l1;
    }
}

// ---------------- device scratch ----------------
__device__ float g_x[NN * C];
__device__ float g_xag[NN * C];
__device__ float g_a[NN * C];
__device__ float g_ares[NN];
__device__ float g_xv2[NN * C];
__device__ float g_u[NN * C];
__device__ float g_v[NN * C];
__device__ float g_h[NN * C];
__device__ float g_s[NN * C];
__device__ int   g_cnt[3][NN];
__device__ int2  g_elist[9][EE];
__device__ int   g_count[9];

// ---------------- zero / classify ----------------
__global__ void zero_all(float4* out4) {
    const long A4 = (long)NN * C / 4;
    const long O4 = (long)MOUT * C / 4;
    const long C4 = 3L * NN / 4;
    const long total = 3 * A4 + O4 + C4;
    float4 z = make_float4(0.f, 0.f, 0.f, 0.f);
    for (long i = blockIdx.x * (long)blockDim.x + threadIdx.x; i < total;
         i += (long)gridDim.x * blockDim.x) {
        if (i < A4)               ((float4*)g_xag)[i] = z;
        else if (i < 2 * A4)      ((float4*)g_a)[i - A4] = z;
        else if (i < 3 * A4)      ((float4*)g_xv2)[i - 2 * A4] = z;
        else if (i < 3 * A4 + O4) out4[i - 3 * A4] = z;
        else                      ((float4*)g_cnt)[i - 3 * A4 - O4] = z;
    }
    if (blockIdx.x == 0 && threadIdx.x < 9) g_count[threadIdx.x] = 0;
}
__global__ void zero_hs() {
    const long A4 = (long)NN * C / 4;
    float4 z = make_float4(0.f, 0.f, 0.f, 0.f);
    for (long i = blockIdx.x * (long)blockDim.x + threadIdx.x; i < 2 * A4;
         i += (long)gridDim.x * blockDim.x) {
        if (i < A4) ((float4*)g_h)[i] = z;
        else        ((float4*)g_s)[i - A4] = z;
    }
}
__global__ void classify_k(const int* __restrict__ ei, const int* __restrict__ attr) {
    int e = blockIdx.x * blockDim.x + threadIdx.x;
    if (e >= EE) return;
    int a = attr[e];
    int2 p = make_int2(ei[e], ei[EE + e]);
    if (a == -3) { int i = atomicAdd(&g_count[0], 1); g_elist[0][i] = p; }
    if (a == -2) { int i = atomicAdd(&g_count[1], 1); g_elist[1][i] = p; }
    if (a == 3)  { int i = atomicAdd(&g_count[2], 1); g_elist[2][i] = p; }
    bool m1 = (a >= 0) && (a <= 1);
    bool m2 = (a >= -1) && (a <= 0);
    bool m3 = (a >= -1) && (a <= 1);
    bool dout = (p.y < NVT) && (((p.y >> 7) % 3) == 0);
    if (m1) { int i = atomicAdd(&g_count[3], 1); g_elist[3][i] = p; atomicAdd(&g_cnt[0][p.y], 1);
              if (dout) { int j = atomicAdd(&g_count[6], 1); g_elist[6][j] = p; } }
    if (m2) { int i = atomicAdd(&g_count[4], 1); g_elist[4][i] = p; atomicAdd(&g_cnt[1][p.y], 1);
              if (dout) { int j = atomicAdd(&g_count[7], 1); g_elist[7][j] = p; } }
    if (m3) { int i = atomicAdd(&g_count[5], 1); g_elist[5][i] = p; atomicAdd(&g_cnt[2][p.y], 1);
              if (dout) { int j = atomicAdd(&g_count[8], 1); g_elist[8][j] = p; } }
}

// ---------------- mma GEMM kernels (BK=64, 2 CTAs/SM) ----------------

// proj: g_x = [xv;xa] @ W + b   (K=1024 -> 16 k-halves over 8 presplit mats)
__global__ __launch_bounds__(256, 2) void proj_mma(
    const float* __restrict__ xv, const float* __restrict__ xa,
    const float* __restrict__ bv, const float* __restrict__ ba) {
    extern __shared__ uint32_t sw[];
    int rowBase = blockIdx.x * 128;
    bool vis = rowBase < NVT;
    const float* X = vis ? (xv + (size_t)rowBase * FDIM) : (xa + (size_t)(rowBase - NVT) * FDIM);
    const float* bias = vis ? bv : ba;
    int matBase = vis ? 0 : 8;
    int tid = threadIdx.x;
    int r = tid >> 1, q = tid & 1;
    float acc[4][4][4] = {};
    for (int kh = 0; kh < 16; kh++) {
        fill_A64(sw, r, q, X + (size_t)r * FDIM + kh * 64 + q * 32, 0);
        fill_B64(sw, matBase + (kh >> 1), kh & 1);
        __syncthreads();
        gemm_tile64(sw, acc);
        __syncthreads();
    }
    int lane = tid & 31, wid = tid >> 5, wm = wid & 1, wn = wid >> 1;
    int g = lane >> 2, t = lane & 3;
#pragma unroll
    for (int mt = 0; mt < 4; mt++) {
        int row = rowBase + wm * 64 + mt * 16 + g;
#pragma unroll
        for (int nt = 0; nt < 4; nt++) {
            int col = wn * 32 + nt * 8 + 2 * t;
            *(float2*)(g_x + (size_t)row * C + col) =
                make_float2(acc[mt][nt][0] + bias[col], acc[mt][nt][1] + bias[col + 1]);
            *(float2*)(g_x + (size_t)(row + 8) * C + col) =
                make_float2(acc[mt][nt][2] + bias[col], acc[mt][nt][3] + bias[col + 1]);
        }
    }
}

// node dual: Ou = act(A)@W[mat0]+bias, Ov = act(A)@W[mat0+1]
__global__ __launch_bounds__(256, 2) void node_dual_mma(
    const float* __restrict__ A, int mat0,
    const float* __restrict__ bias, float* __restrict__ Ou, float* __restrict__ Ov, int relu) {
    extern __shared__ uint32_t sw[];
    int rowBase = blockIdx.x * 128;
    int tid = threadIdx.x;
    int r = tid >> 1, q = tid & 1;
    int lane = tid & 31, wid = tid >> 5, wm = wid & 1, wn = wid >> 1;
    int g = lane >> 2, t = lane & 3;
    for (int half = 0; half < 2; half++) {
        float acc[4][4][4] = {};
        for (int kh = 0; kh < 2; kh++) {
            fill_A64(sw, r, q, A + (size_t)(rowBase + r) * C + kh * 64 + q * 32, relu);
            fill_B64(sw, mat0 + half, kh);
            __syncthreads();
            gemm_tile64(sw, acc);
            __syncthreads();
        }
        float* O = half ? Ov : Ou;
#pragma unroll
        for (int mt = 0; mt < 4; mt++) {
            int row = rowBase + wm * 64 + mt * 16 + g;
#pragma unroll
            for (int nt = 0; nt < 4; nt++) {
                int col = wn * 32 + nt * 8 + 2 * t;
                float b0 = half ? 0.f : bias[col];
                float b1 = half ? 0.f : bias[col + 1];
                *(float2*)(O + (size_t)row * C + col) = make_float2(acc[mt][nt][0] + b0, acc[mt][nt][1] + b1);
                *(float2*)(O + (size_t)(row + 8) * C + col) = make_float2(acc[mt][nt][2] + b0, acc[mt][nt][3] + b1);
            }
        }
    }
}

// edge: z = relu(u[d]+v[s]-v[d]); w = z@W2 + b2; atomicMax(>0) into Out[d]
__global__ __launch_bounds__(256, 2) void edge_mma(
    int li, int mat, const float* __restrict__ b2,
    const float* __restrict__ U, const float* __restrict__ V, float* __restrict__ Out) {
    int cnt = g_count[li];
    int base = blockIdx.x * 128;
    if (base >= cnt) return;
    extern __shared__ uint32_t sw[];
    __shared__ int2 sd[128];
    __shared__ float bsh[128];
    int tid = threadIdx.x;
    if (tid < 128) {
        int e = base + tid;
        sd[tid] = (e < cnt) ? g_elist[li][e] : make_int2(-1, -1);
        bsh[tid] = b2[tid];
    }
    __syncthreads();
    int r = tid >> 1, q = tid & 1;
    int2 p = sd[r];
    float acc[4][4][4] = {};
    for (int kh = 0; kh < 2; kh++) {
        int ko = kh * 64 + q * 32;
        uint32_t* aH = sw + r * RSW + q * 16;
        uint32_t* aL = aH + PLANE;
        if (p.y >= 0) {
            const float* u = U + (size_t)p.y * C + ko;
            const float* vs = V + (size_t)p.x * C + ko;
            const float* vd = V + (size_t)p.y * C + ko;
#pragma unroll 2
            for (int k = 0; k < 32; k += 4) {
                float4 a = *(const float4*)(u + k);
                float4 b = *(const float4*)(vs + k);
                float4 c = *(const float4*)(vd + k);
                float z0 = fmaxf(a.x + b.x - c.x, 0.f);
                float z1 = fmaxf(a.y + b.y - c.y, 0.f);
                float z2 = fmaxf(a.z + b.z - c.z, 0.f);
                float z3 = fmaxf(a.w + b.w - c.w, 0.f);
                uint32_t h0, l0, h1, l1;
                split2(z0, z1, h0, l0);
                split2(z2, z3, h1, l1);
                aH[k / 2] = h0; aH[k / 2 + 1] = h1;
                aL[k / 2] = l0; aL[k / 2 + 1] = l1;
            }
        } else {
#pragma unroll 2
            for (int k = 0; k < 32; k += 4) {
                aH[k / 2] = 0; aH[k / 2 + 1] = 0;
                aL[k / 2] = 0; aL[k / 2 + 1] = 0;
            }
        }
        fill_B64(sw, mat, kh);
        __syncthreads();
        gemm_tile64(sw, acc);
        __syncthreads();
    }
    int lane = tid & 31, wid = tid >> 5, wm = wid & 1, wn = wid >> 1;
    int g = lane >> 2, t = lane & 3;
#pragma unroll
    for (int mt = 0; mt < 4; mt++) {
        int rl = wm * 64 + mt * 16 + g;
        int2 q0 = sd[rl];
        int2 q1 = sd[rl + 8];
#pragma unroll
        for (int nt = 0; nt < 4; nt++) {
            int col = wn * 32 + nt * 8 + 2 * t;
            if (q0.y >= 0) {
                unsigned int* orow = (unsigned int*)(Out + (size_t)q0.y * C);
                float v0 = acc[mt][nt][0] + bsh[col];
                float v1 = acc[mt][nt][1] + bsh[col + 1];
                if (v0 > 0.f) atomicMax(orow + col, __float_as_uint(v0));
                if (v1 > 0.f) atomicMax(orow + col + 1, __float_as_uint(v1));
            }
            if (q1.y >= 0) {
                unsigned int* orow = (unsigned int*)(Out + (size_t)q1.y * C);
                float v2 = acc[mt][nt][2] + bsh[col];
                float v3 = acc[mt][nt][3] + bsh[col + 1];
                if (v2 > 0.f) atomicMax(orow + col, __float_as_uint(v2));
                if (v3 > 0.f) atomicMax(orow + col + 1, __float_as_uint(v3));
            }
        }
    }
}

// final: out[r] += relu((s[n]/cnt)@Wl + bl + h[n]@Wr)
__global__ __launch_bounds__(256, 2) void final_mma(
    const float* __restrict__ bl, int branch, float* __restrict__ out) {
    extern __shared__ uint32_t sw[];
    int rowBase = blockIdx.x * 128;
    int tid = threadIdx.x;
    int r = tid >> 1, q = tid & 1;
    int rr = rowBase + r;
    int n = (rr >> 7) * 384 + (rr & 127);
    int cv = g_cnt[branch][n];
    float inv = 1.0f / (float)(cv > 1 ? cv : 1);
    float acc[4][4][4] = {};
    for (int ph = 0; ph < 2; ph++) {
        const float* src = (ph == 0) ? (g_s + (size_t)n * C) : (g_h + (size_t)n * C);
        float scale = (ph == 0) ? inv : 1.0f;
        int mat = 28 + ph;
        for (int kh = 0; kh < 2; kh++) {
            int ko = kh * 64 + q * 32;
            uint32_t* aH = sw + r * RSW + q * 16;
            uint32_t* aL = aH + PLANE;
#pragma unroll 2
            for (int k = 0; k < 32; k += 4) {
                float4 v = *(const float4*)(src + ko + k);
                uint32_t h0, l0, h1, l1;
                split2(v.x * scale, v.y * scale, h0, l0);
                split2(v.z * scale, v.w * scale, h1, l1);
                aH[k / 2] = h0; aH[k / 2 + 1] = h1;
                aL[k / 2] = l0; aL[k / 2 + 1] = l1;
            }
            fill_B64(sw, mat, kh);
            __syncthreads();
            gemm_tile64(sw, acc);
            __syncthreads();
        }
    }
    int lane = tid & 31, wid = tid >> 5, wm = wid & 1, wn = wid >> 1;
    int g = lane >> 2, t = lane & 3;
#pragma unroll
    for (int mt = 0; mt < 4; mt++) {
        int row = rowBase + wm * 64 + mt * 16 + g;
#pragma unroll
        for (int nt = 0; nt < 4; nt++) {
            int col = wn * 32 + nt * 8 + 2 * t;
            float2 o0 = *(float2*)(out + (size_t)row * C + col);
            o0.x += fmaxf(acc[mt][nt][0] + bl[col], 0.f);
            o0.y += fmaxf(acc[mt][nt][1] + bl[col + 1], 0.f);
            *(float2*)(out + (size_t)row * C + col) = o0;
            float2 o1 = *(float2*)(out + (size_t)(row + 8) * C + col);
            o1.x += fmaxf(acc[mt][nt][2] + bl[col], 0.f);
            o1.y += fmaxf(acc[mt][nt][3] + bl[col + 1], 0.f);
            *(float2*)(out + (size_t)(row + 8) * C + col) = o1;
        }
    }
}

// ---------------- warp-per-edge aggregations ----------------
__global__ void agg_vpa() {
    int cnt = g_count[0];
    int nw = gridDim.x * (blockDim.x >> 5);
    int w = blockIdx.x * (blockDim.x >> 5) + (threadIdx.x >> 5);
    int lane = threadIdx.x & 31;
    for (int e = w; e < cnt; e += nw) {
        int2 p = g_elist[0][e];
        float4 a = *(const float4*)(g_x + (size_t)p.x * C + lane * 4);
        float4 b = *(const float4*)(g_x + (size_t)p.y * C + lane * 4);
        unsigned int* o = (unsigned int*)(g_xag + (size_t)p.y * C + lane * 4);
        float m;
        m = a.x + b.x; if (m > 0.f) atomicMax(o + 0, __float_as_uint(m));
        m = a.y + b.y; if (m > 0.f) atomicMax(o + 1, __float_as_uint(m));
        m = a.z + b.z; if (m > 0.f) atomicMax(o + 2, __float_as_uint(m));
        m = a.w + b.w; if (m > 0.f) atomicMax(o + 3, __float_as_uint(m));
    }
}
__global__ void ares_k(const float* __restrict__ fcW, const float* __restrict__ fcb) {
    int n = blockIdx.x * (blockDim.x >> 5) + (threadIdx.x >> 5);
    if (n >= NN) return;
    int lane = threadIdx.x & 31;
    float4 a4 = *(const float4*)(g_a + (size_t)n * C + lane * 4);
    float4 w4 = *(const float4*)(fcW + lane * 4);
    float s = a4.x * w4.x + a4.y * w4.y + a4.z * w4.z + a4.w * w4.w;
#pragma unroll
    for (int o = 16; o; o >>= 1) s += __shfl_xor_sync(0xffffffffu, s, o);
    if (lane == 0) g_ares[n] = s + fcb[0];
}
__global__ void agg_acv() {
    int cnt = g_count[2];
    int nw = gridDim.x * (blockDim.x >> 5);
    int w = blockIdx.x * (blockDim.x >> 5) + (threadIdx.x >> 5);
    int lane = threadIdx.x & 31;
    for (int e = w; e < cnt; e += nw) {
        int2 p = g_elist[2][e];
        float wgt = g_ares[p.x];
        float4 a = *(const float4*)(g_x + (size_t)p.x * C + lane * 4);
        float4 b = *(const float4*)(g_x + (size_t)p.y * C + lane * 4);
        float* o = g_xv2 + (size_t)p.y * C + lane * 4;
        atomicAdd(o + 0, wgt * a.x + b.x);
        atomicAdd(o + 1, wgt * a.y + b.y);
        atomicAdd(o + 2, wgt * a.z + b.z);
        atomicAdd(o + 3, wgt * a.w + b.w);
    }
}
__global__ void agg_sage(int li) {
    int cnt = g_count[li];
    int nw = gridDim.x * (blockDim.x >> 5);
    int w = blockIdx.x * (blockDim.x >> 5) + (threadIdx.x >> 5);
    int lane = threadIdx.x & 31;
    for (int e = w; e < cnt; e += nw) {
        int2 p = g_elist[li][e];
        float4 hv = *(const float4*)(g_h + (size_t)p.x * C + lane * 4);
        float* o = g_s + (size_t)p.y * C + lane * 4;
        atomicAdd(o + 0, hv.x);
        atomicAdd(o + 1, hv.y);
        atomicAdd(o + 2, hv.z);
        atomicAdd(o + 3, hv.w);
    }
}

// ---------------- launch ----------------
extern "C" void kernel_launch(void* const* d_in, const int* in_sizes, int n_in,
                              void* d_out, int out_size) {
    (void)in_sizes; (void)n_in; (void)out_size;
    const float* xv = (const float*)d_in[0];
    const float* xa = (const float*)d_in[1];
    const float* b011 = (const float*)d_in[3];
    const float* b012 = (const float*)d_in[5];
    const float* ecA_b1 = (const float*)d_in[7];
    const float* ecA_b2 = (const float*)d_in[9];
    const float* sage_bl = (const float*)d_in[23];
    const float* fc_W = (const float*)d_in[25];
    const float* fc_b = (const float*)d_in[26];
    const int* edge_index = (const int*)d_in[27];
    const int* edge_attr = (const int*)d_in[28];
    float* out = (float*)d_out;

    WPtrs P;
    P.p[0] = (const float*)d_in[2];
    P.p[1] = (const float*)d_in[4];
    P.p[2] = (const float*)d_in[6];
    P.p[3] = (const float*)d_in[8];
    P.p[4] = (const float*)d_in[10];
    P.p[5] = (const float*)d_in[12];
    P.p[6] = (const float*)d_in[14];
    P.p[7] = (const float*)d_in[16];
    P.p[8] = (const float*)d_in[18];
    P.p[9] = (const float*)d_in[20];
    P.p[10] = (const float*)d_in[22];
    P.p[11] = (const float*)d_in[24];

    cudaFuncSetAttribute(prep_w, cudaFuncAttributeMaxDynamicSharedMemorySize, 128 * 132 * 4);
    cudaFuncSetAttribute(proj_mma, cudaFuncAttributeMaxDynamicSharedMemorySize, SMEM_BYTES);
    cudaFuncSetAttribute(node_dual_mma, cudaFuncAttributeMaxDynamicSharedMemorySize, SMEM_BYTES);
    cudaFuncSetAttribute(edge_mma, cudaFuncAttributeMaxDynamicSharedMemorySize, SMEM_BYTES);
    cudaFuncSetAttribute(final_mma, cudaFuncAttributeMaxDynamicSharedMemorySize, SMEM_BYTES);

    float *pxag, *pxv2, *pa, *pu, *pv, *ph;
    cudaGetSymbolAddress((void**)&pxag, g_xag);
    cudaGetSymbolAddress((void**)&pxv2, g_xv2);
    cudaGetSymbolAddress((void**)&pa, g_a);
    cudaGetSymbolAddress((void**)&pu, g_u);
    cudaGetSymbolAddress((void**)&pv, g_v);
    cudaGetSymbolAddress((void**)&ph, g_h);

    zero_all<<<8192, 256>>>((float4*)d_out);
    prep_w<<<30, 256, 128 * 132 * 4>>>(P);
    classify_k<<<(EE + 255) / 256, 256>>>(edge_index, edge_attr);
    proj_mma<<<NN / 128, 256, SMEM_BYTES>>>(xv, xa, b011, b012);

    agg_vpa<<<2048, 256>>>();

    node_dual_mma<<<NN / 128, 256, SMEM_BYTES>>>(pxag, 16, ecA_b1, pu, pv, 0);
    edge_mma<<<2048, 256, SMEM_BYTES>>>(1, 18, ecA_b2, pu, pv, pa);
    ares_k<<<NN / 8, 256>>>(fc_W, fc_b);

    agg_acv<<<2048, 256>>>();

    for (int k = 0; k < 3; k++) {
        const float* b1 = (const float*)d_in[11 + 4 * k];
        const float* b2 = (const float*)d_in[13 + 4 * k];
        zero_hs<<<8192, 256>>>();
        node_dual_mma<<<NN / 128, 256, SMEM_BYTES>>>(pxv2, 19 + 3 * k, b1, pu, pv, 1);
        edge_mma<<<2048, 256, SMEM_BYTES>>>(3 + k, 21 + 3 * k, b2, pu, pv, ph);
        agg_sage<<<2048, 256>>>(6 + k);
        final_mma<<<MOUT / 128, 256, SMEM_BYTES>>>(sage_bl, k, out);
    }
}

// round 7
// speedup vs baseline: 1.7370x; 1.0010x over previous
#include <cuda_runtime.h>
#include <cuda_bf16.h>
#include <cstdint>

#define NVIS 192
#define NAUD 64
#define TT   128
#define FDIM 1024
#define C    128
#define EE   262144
#define NN   32768
#define NVT  24576
#define MOUT 8192

// BK=64 tile: 4 planes (Ahi, Alo, Bhi, Blo), each 128 rows x 32 bf16x2 words,
// row stride 36 words (144B = 9*16B) -> conflict-free, 16B-aligned ldmatrix rows.
#define RSW   36
#define PLANE (128 * RSW)          // 4608 words per plane
#define SMEM_BYTES (4 * PLANE * 4) // 73728 -> 2 CTAs/SM

// proj adds an A staging buffer: 256 threads x 36 words (144B, 16B-aligned)
#define ASTAGE_OFF (4 * PLANE)
#define ASTR 36
#define SMEM_PROJ ((4 * PLANE + 256 * ASTR) * 4)   // 110592 -> still 2 CTAs/SM

// ---------------- helpers ----------------
__device__ __forceinline__ void split2(float x, float y, uint32_t& hi, uint32_t& lo) {
    __nv_bfloat16 hx = __float2bfloat16(x), hy = __float2bfloat16(y);
    __nv_bfloat16 lx = __float2bfloat16(x - __bfloat162float(hx));
    __nv_bfloat16 ly = __float2bfloat16(y - __bfloat162float(hy));
    hi = (uint32_t)*(uint16_t*)&hx | ((uint32_t)*(uint16_t*)&hy << 16);
    lo = (uint32_t)*(uint16_t*)&lx | ((uint32_t)*(uint16_t*)&ly << 16);
}

__device__ __forceinline__ void mma_bf16(float* c, const uint32_t* a, uint32_t b0, uint32_t b1) {
    asm volatile(
        "mma.sync.aligned.m16n8k16.row.col.f32.bf16.bf16.f32 "
        "{%0,%1,%2,%3}, {%4,%5,%6,%7}, {%8,%9}, {%0,%1,%2,%3};"
        : "+f"(c[0]), "+f"(c[1]), "+f"(c[2]), "+f"(c[3])
        : "r"(a[0]), "r"(a[1]), "r"(a[2]), "r"(a[3]), "r"(b0), "r"(b1));
}

#define LDSM_X4(r, a) \
    asm volatile("ldmatrix.sync.aligned.m8n8.x4.shared.b16 {%0,%1,%2,%3}, [%4];" \
        : "=r"((r)[0]), "=r"((r)[1]), "=r"((r)[2]), "=r"((r)[3]) : "r"(a))
#define LDSM_X2(r, a) \
    asm volatile("ldmatrix.sync.aligned.m8n8.x2.shared.b16 {%0,%1}, [%2];" \
        : "=r"((r)[0]), "=r"((r)[1]) : "r"(a))

#define CP_ASYNC16(dst, src) \
    asm volatile("cp.async.ca.shared.global [%0], [%1], 16;" :: "r"(dst), "l"(src))
#define CP_COMMIT() asm volatile("cp.async.commit_group;" ::: "memory")
#define CP_WAIT0()  asm volatile("cp.async.wait_group 0;" ::: "memory")

__device__ __forceinline__ uint32_t s2u(const void* p) {
    unsigned long long x;
    asm("cvta.to.shared.u64 %0, %1;" : "=l"(x) : "l"(p));
    return (uint32_t)x;
}

// 128x128x64 tile GEMM: acc += A @ B^T, 3-pass bf16 split, ldmatrix feed.
__device__ __forceinline__ void gemm_tile64(const uint32_t* sw, float acc[4][4][4]) {
    int lane = threadIdx.x & 31, wid = threadIdx.x >> 5;
    int wm = wid & 1, wn = wid >> 1;   // warp grid 2(m) x 4(n)
    uint32_t swb = s2u(sw);
    int ar = wm * 64 + (lane & 15);
    int ac = (lane >> 4) * 4;
    uint32_t aH = swb + (uint32_t)((ar * RSW + ac) << 2);
    uint32_t aL = aH + PLANE * 4;
    int br = wn * 32 + (lane & 7);
    int bc = ((lane >> 3) & 1) * 4;
    uint32_t bH = swb + 2u * PLANE * 4 + (uint32_t)((br * RSW + bc) << 2);
    uint32_t bL = bH + PLANE * 4;
#pragma unroll
    for (int ks = 0; ks < 4; ks++) {
        uint32_t kb = (uint32_t)(ks * 8 * 4);
        uint32_t bh[4][2], bl[4][2];
#pragma unroll
        for (int nt = 0; nt < 4; nt++) {
            LDSM_X2(bh[nt], bH + (uint32_t)(nt * 8 * RSW * 4) + kb);
            LDSM_X2(bl[nt], bL + (uint32_t)(nt * 8 * RSW * 4) + kb);
        }
#pragma unroll
        for (int mt = 0; mt < 4; mt++) {
            uint32_t ah[4], al[4];
            LDSM_X4(ah, aH + (uint32_t)(mt * 16 * RSW * 4) + kb);
            LDSM_X4(al, aL + (uint32_t)(mt * 16 * RSW * 4) + kb);
#pragma unroll
            for (int nt = 0; nt < 4; nt++) {
                mma_bf16(acc[mt][nt], ah, bh[nt][0], bh[nt][1]);
                mma_bf16(acc[mt][nt], ah, bl[nt][0], bl[nt][1]);
                mma_bf16(acc[mt][nt], al, bh[nt][0], bh[nt][1]);
            }
        }
    }
}

// ---------------- presplit weights ----------------
__device__ uint32_t g_wsplit[30][2][128][64];

struct WPtrs { const float* p[12]; };

__global__ __launch_bounds__(256) void prep_w(WPtrs P) {
    extern __shared__ float st[];  // [128][132]
    int m = blockIdx.x, tid = threadIdx.x;
    const float* W;
    if (m < 8)       W = P.p[0] + (size_t)m * 128 * C;
    else if (m < 16) W = P.p[1] + (size_t)(m - 8) * 128 * C;
    else {
        int r = m - 16;
        if (r < 12) {
            int cvi = r / 3, w = r % 3;
            const float* W1 = P.p[2 + 2 * cvi];
            const float* W2 = P.p[3 + 2 * cvi];
            W = (w < 2) ? (W1 + (size_t)w * 128 * C) : W2;
        } else W = (r == 12) ? P.p[10] : P.p[11];
    }
    for (int i = tid; i < 128 * 32; i += 256) {
        int row = i >> 5, c4 = i & 31;
        float4 v = *(const float4*)(W + (size_t)row * C + c4 * 4);
        st[row * 132 + c4 * 4 + 0] = v.x;
        st[row * 132 + c4 * 4 + 1] = v.y;
        st[row * 132 + c4 * 4 + 2] = v.z;
        st[row * 132 + c4 * 4 + 3] = v.w;
    }
    __syncthreads();
    for (int i = tid; i < 128 * 64; i += 256) {
        int n = i >> 6, j = i & 63;
        uint32_t h, l;
        split2(st[(2 * j) * 132 + n], st[(2 * j + 1) * 132 + n], h, l);
        g_wsplit[m][0][n][j] = h;
        g_wsplit[m][1][n][j] = l;
    }
}

// copy one K-half (32 kpairs) of presplit B planes into smem
__device__ __forceinline__ void fill_B64(uint32_t* sw, int mat, int half) {
    int tid = threadIdx.x;
#pragma unroll
    for (int it = 0; it < 8; it++) {
        int idx = tid + it * 256;          // over [2][128][8] float4 units
        int pl = idx >> 10, rem = idx & 1023;
        int n = rem >> 3, f = rem & 7;
        float4 v = *(const float4*)&g_wsplit[mat][pl][n][half * 32 + f * 4];
        *(float4*)&sw[(2 + pl) * PLANE + n * RSW + f * 4] = v;
    }
}

// fill 32 k-values of A row r (quarter q) from gmem src (with optional relu)
__device__ __forceinline__ void fill_A64(uint32_t* sw, int r, int q,
                                         const float* __restrict__ src, int relu) {
    uint32_t* aH = sw + r * RSW + q * 16;
    uint32_t* aL = aH + PLANE;
#pragma unroll 2
    for (int k = 0; k < 32; k += 4) {
        float4 v = *(const float4*)(src + k);
        if (relu) { v.x = fmaxf(v.x, 0.f); v.y = fmaxf(v.y, 0.f); v.z = fmaxf(v.z, 0.f); v.w = fmaxf(v.w, 0.f); }
        uint32_t h0, l0, h1, l1;
        split2(v.x, v.y, h0, l0);
        split2(v.z, v.w, h1, l1);
        aH[k / 2] = h0; aH[k / 2 + 1] = h1;
        aL[k / 2] = l0; aL[k / 2 + 1] = l1;
    }
}

// ---------------- device scratch ----------------
__device__ float g_x[NN * C];
__device__ float g_xag[NN * C];
__device__ float g_a[NN * C];
__device__ float g_ares[NN];
__device__ float g_xv2[NN * C];
__device__ float g_u[NN * C];     // holds w = u + b1 - v
__device__ float g_v[NN * C];
__device__ float g_h[NN * C];
__device__ float g_s[NN * C];
__device__ int   g_cnt[3][NN];
__device__ int2  g_elist[9][EE];
__device__ int   g_count[9];

// ---------------- zero / classify ----------------
__global__ void zero_all(float4* out4) {
    const long A4 = (long)NN * C / 4;
    const long O4 = (long)MOUT * C / 4;
    const long C4 = 3L * NN / 4;
    const long total = 3 * A4 + O4 + C4;
    float4 z = make_float4(0.f, 0.f, 0.f, 0.f);
    for (long i = blockIdx.x * (long)blockDim.x + threadIdx.x; i < total;
         i += (long)gridDim.x * blockDim.x) {
        if (i < A4)               ((float4*)g_xag)[i] = z;
        else if (i < 2 * A4)      ((float4*)g_a)[i - A4] = z;
        else if (i < 3 * A4)      ((float4*)g_xv2)[i - 2 * A4] = z;
        else if (i < 3 * A4 + O4) out4[i - 3 * A4] = z;
        else                      ((float4*)g_cnt)[i - 3 * A4 - O4] = z;
    }
    if (blockIdx.x == 0 && threadIdx.x < 9) g_count[threadIdx.x] = 0;
}
__global__ void zero_hs() {
    const long A4 = (long)NN * C / 4;
    float4 z = make_float4(0.f, 0.f, 0.f, 0.f);
    for (long i = blockIdx.x * (long)blockDim.x + threadIdx.x; i < 2 * A4;
         i += (long)gridDim.x * blockDim.x) {
        if (i < A4) ((float4*)g_h)[i] = z;
        else        ((float4*)g_s)[i - A4] = z;
    }
}
__global__ void classify_k(const int* __restrict__ ei, const int* __restrict__ attr) {
    int e = blockIdx.x * blockDim.x + threadIdx.x;
    if (e >= EE) return;
    int a = attr[e];
    int2 p = make_int2(ei[e], ei[EE + e]);
    if (a == -3) { int i = atomicAdd(&g_count[0], 1); g_elist[0][i] = p; }
    if (a == -2) { int i = atomicAdd(&g_count[1], 1); g_elist[1][i] = p; }
    if (a == 3)  { int i = atomicAdd(&g_count[2], 1); g_elist[2][i] = p; }
    bool m1 = (a >= 0) && (a <= 1);
    bool m2 = (a >= -1) && (a <= 0);
    bool m3 = (a >= -1) && (a <= 1);
    bool dout = (p.y < NVT) && (((p.y >> 7) % 3) == 0);
    if (m1) { int i = atomicAdd(&g_count[3], 1); g_elist[3][i] = p; atomicAdd(&g_cnt[0][p.y], 1);
              if (dout) { int j = atomicAdd(&g_count[6], 1); g_elist[6][j] = p; } }
    if (m2) { int i = atomicAdd(&g_count[4], 1); g_elist[4][i] = p; atomicAdd(&g_cnt[1][p.y], 1);
              if (dout) { int j = atomicAdd(&g_count[7], 1); g_elist[7][j] = p; } }
    if (m3) { int i = atomicAdd(&g_count[5], 1); g_elist[5][i] = p; atomicAdd(&g_cnt[2][p.y], 1);
              if (dout) { int j = atomicAdd(&g_count[8], 1); g_elist[8][j] = p; } }
}

// ---------------- mma GEMM kernels (BK=64, 2 CTAs/SM) ----------------

// proj: g_x = [xv;xa] @ W + b   (K=1024, cp.async pipelined A)
__global__ __launch_bounds__(256, 2) void proj_mma(
    const float* __restrict__ xv, const float* __restrict__ xa,
    const float* __restrict__ bv, const float* __restrict__ ba) {
    extern __shared__ uint32_t sw[];
    int rowBase = blockIdx.x * 128;
    bool vis = rowBase < NVT;
    const float* X = vis ? (xv + (size_t)rowBase * FDIM) : (xa + (size_t)(rowBase - NVT) * FDIM);
    const float* bias = vis ? bv : ba;
    int matBase = vis ? 0 : 8;
    int tid = threadIdx.x;
    int r = tid >> 1, q = tid & 1;
    float* ast = (float*)(sw + ASTAGE_OFF) + tid * ASTR;
    uint32_t astu = s2u(ast);
    const float* src0 = X + (size_t)r * FDIM + q * 32;

    // prologue: stage kh=0
#pragma unroll
    for (int k = 0; k < 32; k += 4) CP_ASYNC16(astu + k * 4, src0 + k);
    CP_COMMIT();

    float acc[4][4][4] = {};
    for (int kh = 0; kh < 16; kh++) {
        CP_WAIT0();
        __syncthreads();            // astage ready AND previous gemm done
        // split staged A -> planes
        uint32_t* aH = sw + r * RSW + q * 16;
        uint32_t* aL = aH + PLANE;
#pragma unroll 2
        for (int k = 0; k < 32; k += 4) {
            float4 v = *(float4*)(ast + k);
            uint32_t h0, l0, h1, l1;
            split2(v.x, v.y, h0, l0);
            split2(v.z, v.w, h1, l1);
            aH[k / 2] = h0; aH[k / 2 + 1] = h1;
            aL[k / 2] = l0; aL[k / 2 + 1] = l1;
        }
        fill_B64(sw, matBase + (kh >> 1), kh & 1);
        __syncthreads();
        if (kh < 15) {
            const float* s2 = src0 + (kh + 1) * 64;
#pragma unroll
            for (int k = 0; k < 32; k += 4) CP_ASYNC16(astu + k * 4, s2 + k);
            CP_COMMIT();
        }
        gemm_tile64(sw, acc);
    }
    int lane = tid & 31, wid = tid >> 5, wm = wid & 1, wn = wid >> 1;
    int g = lane >> 2, t = lane & 3;
#pragma unroll
    for (int mt = 0; mt < 4; mt++) {
        int row = rowBase + wm * 64 + mt * 16 + g;
#pragma unroll
        for (int nt = 0; nt < 4; nt++) {
            int col = wn * 32 + nt * 8 + 2 * t;
            *(float2*)(g_x + (size_t)row * C + col) =
                make_float2(acc[mt][nt][0] + bias[col], acc[mt][nt][1] + bias[col + 1]);
            *(float2*)(g_x + (size_t)(row + 8) * C + col) =
                make_float2(acc[mt][nt][2] + bias[col], acc[mt][nt][3] + bias[col + 1]);
        }
    }
}

// node dual: Ov = act(A)@W[mat0+1] (written first),
//            Ow = act(A)@W[mat0] + bias - Ov  (w-trick for edge gathers)
__global__ __launch_bounds__(256, 2) void node_dual_mma(
    const float* __restrict__ A, int mat0,
    const float* __restrict__ bias, float* __restrict__ Ow, float* __restrict__ Ov, int relu) {
    extern __shared__ uint32_t sw[];
    int rowBase = blockIdx.x * 128;
    int tid = threadIdx.x;
    int r = tid >> 1, q = tid & 1;
    int lane = tid & 31, wid = tid >> 5, wm = wid & 1, wn = wid >> 1;
    int g = lane >> 2, t = lane & 3;
    for (int hsel = 0; hsel < 2; hsel++) {
        int half = 1 - hsel;   // v first, then u
        float acc[4][4][4] = {};
        for (int kh = 0; kh < 2; kh++) {
            fill_A64(sw, r, q, A + (size_t)(rowBase + r) * C + kh * 64 + q * 32, relu);
            fill_B64(sw, mat0 + half, kh);
            __syncthreads();
            gemm_tile64(sw, acc);
            __syncthreads();
        }
#pragma unroll
        for (int mt = 0; mt < 4; mt++) {
            int row = rowBase + wm * 64 + mt * 16 + g;
#pragma unroll
            for (int nt = 0; nt < 4; nt++) {
                int col = wn * 32 + nt * 8 + 2 * t;
                if (half == 1) {
                    *(float2*)(Ov + (size_t)row * C + col) = make_float2(acc[mt][nt][0], acc[mt][nt][1]);
                    *(float2*)(Ov + (size_t)(row + 8) * C + col) = make_float2(acc[mt][nt][2], acc[mt][nt][3]);
                } else {
                    float2 v0 = *(float2*)(Ov + (size_t)row * C + col);        // own writes
                    float2 v1 = *(float2*)(Ov + (size_t)(row + 8) * C + col);
                    *(float2*)(Ow + (size_t)row * C + col) =
                        make_float2(acc[mt][nt][0] + bias[col] - v0.x, acc[mt][nt][1] + bias[col + 1] - v0.y);
                    *(float2*)(Ow + (size_t)(row + 8) * C + col) =
                        make_float2(acc[mt][nt][2] + bias[col] - v1.x, acc[mt][nt][3] + bias[col + 1] - v1.y);
                }
            }
        }
    }
}

// edge: z = relu(w[d] + v[s]); out = z@W2 + b2; atomicMax(>0) into Out[d]
__global__ __launch_bounds__(256, 2) void edge_mma(
    int li, int mat, const float* __restrict__ b2,
    const float* __restrict__ W, const float* __restrict__ V, float* __restrict__ Out) {
    int cnt = g_count[li];
    int base = blockIdx.x * 128;
    if (base >= cnt) return;
    extern __shared__ uint32_t sw[];
    __shared__ int2 sd[128];
    __shared__ float bsh[128];
    int tid = threadIdx.x;
    if (tid < 128) {
        int e = base + tid;
        sd[tid] = (e < cnt) ? g_elist[li][e] : make_int2(-1, -1);
        bsh[tid] = b2[tid];
    }
    __syncthreads();
    int r = tid >> 1, q = tid & 1;
    int2 p = sd[r];
    float acc[4][4][4] = {};
    for (int kh = 0; kh < 2; kh++) {
        int ko = kh * 64 + q * 32;
        uint32_t* aH = sw + r * RSW + q * 16;
        uint32_t* aL = aH + PLANE;
        if (p.y >= 0) {
            const float* wr = W + (size_t)p.y * C + ko;
            const float* vs = V + (size_t)p.x * C + ko;
#pragma unroll 2
            for (int k = 0; k < 32; k += 4) {
                float4 a = *(const float4*)(wr + k);
                float4 b = *(const float4*)(vs + k);
                float z0 = fmaxf(a.x + b.x, 0.f);
                float z1 = fmaxf(a.y + b.y, 0.f);
                float z2 = fmaxf(a.z + b.z, 0.f);
                float z3 = fmaxf(a.w + b.w, 0.f);
                uint32_t h0, l0, h1, l1;
                split2(z0, z1, h0, l0);
                split2(z2, z3, h1, l1);
                aH[k / 2] = h0; aH[k / 2 + 1] = h1;
                aL[k / 2] = l0; aL[k / 2 + 1] = l1;
            }
        } else {
#pragma unroll 2
            for (int k = 0; k < 32; k += 4) {
                aH[k / 2] = 0; aH[k / 2 + 1] = 0;
                aL[k / 2] = 0; aL[k / 2 + 1] = 0;
            }
        }
        fill_B64(sw, mat, kh);
        __syncthreads();
        gemm_tile64(sw, acc);
        __syncthreads();
    }
    int lane = tid & 31, wid = tid >> 5, wm = wid & 1, wn = wid >> 1;
    int g = lane >> 2, t = lane & 3;
#pragma unroll
    for (int mt = 0; mt < 4; mt++) {
        int rl = wm * 64 + mt * 16 + g;
        int2 q0 = sd[rl];
        int2 q1 = sd[rl + 8];
#pragma unroll
        for (int nt = 0; nt < 4; nt++) {
            int col = wn * 32 + nt * 8 + 2 * t;
            if (q0.y >= 0) {
                unsigned int* orow = (unsigned int*)(Out + (size_t)q0.y * C);
                float v0 = acc[mt][nt][0] + bsh[col];
                float v1 = acc[mt][nt][1] + bsh[col + 1];
                if (v0 > 0.f) atomicMax(orow + col, __float_as_uint(v0));
                if (v1 > 0.f) atomicMax(orow + col + 1, __float_as_uint(v1));
            }
            if (q1.y >= 0) {
                unsigned int* orow = (unsigned int*)(Out + (size_t)q1.y * C);
                float v2 = acc[mt][nt][2] + bsh[col];
                float v3 = acc[mt][nt][3] + bsh[col + 1];
                if (v2 > 0.f) atomicMax(orow + col, __float_as_uint(v2));
                if (v3 > 0.f) atomicMax(orow + col + 1, __float_as_uint(v3));
            }
        }
    }
}

// final: out[r] += relu((s[n]/cnt)@Wl + bl + h[n]@Wr)
__global__ __launch_bounds__(256, 2) void final_mma(
    const float* __restrict__ bl, int branch, float* __restrict__ out) {
    extern __shared__ uint32_t sw[];
    int rowBase = blockIdx.x * 128;
    int tid = threadIdx.x;
    int r = tid >> 1, q = tid & 1;
    int rr = rowBase + r;
    int n = (rr >> 7) * 384 + (rr & 127);
    int cv = g_cnt[branch][n];
    float inv = 1.0f / (float)(cv > 1 ? cv : 1);
    float acc[4][4][4] = {};
    for (int ph = 0; ph < 2; ph++) {
        const float* src = (ph == 0) ? (g_s + (size_t)n * C) : (g_h + (size_t)n * C);
        float scale = (ph == 0) ? inv : 1.0f;
        int mat = 28 + ph;
        for (int kh = 0; kh < 2; kh++) {
            int ko = kh * 64 + q * 32;
            uint32_t* aH = sw + r * RSW + q * 16;
            uint32_t* aL = aH + PLANE;
#pragma unroll 2
            for (int k = 0; k < 32; k += 4) {
                float4 v = *(const float4*)(src + ko + k);
                uint32_t h0, l0, h1, l1;
                split2(v.x * scale, v.y * scale, h0, l0);
                split2(v.z * scale, v.w * scale, h1, l1);
                aH[k / 2] = h0; aH[k / 2 + 1] = h1;
                aL[k / 2] = l0; aL[k / 2 + 1] = l1;
            }
            fill_B64(sw, mat, kh);
            __syncthreads();
            gemm_tile64(sw, acc);
            __syncthreads();
        }
    }
    int lane = tid & 31, wid = tid >> 5, wm = wid & 1, wn = wid >> 1;
    int g = lane >> 2, t = lane & 3;
#pragma unroll
    for (int mt = 0; mt < 4; mt++) {
        int row = rowBase + wm * 64 + mt * 16 + g;
#pragma unroll
        for (int nt = 0; nt < 4; nt++) {
            int col = wn * 32 + nt * 8 + 2 * t;
            float2 o0 = *(float2*)(out + (size_t)row * C + col);
            o0.x += fmaxf(acc[mt][nt][0] + bl[col], 0.f);
            o0.y += fmaxf(acc[mt][nt][1] + bl[col + 1], 0.f);
            *(float2*)(out + (size_t)row * C + col) = o0;
            float2 o1 = *(float2*)(out + (size_t)(row + 8) * C + col);
            o1.x += fmaxf(acc[mt][nt][2] + bl[col], 0.f);
            o1.y += fmaxf(acc[mt][nt][3] + bl[col + 1], 0.f);
            *(float2*)(out + (size_t)(row + 8) * C + col) = o1;
        }
    }
}

// ---------------- warp-per-edge aggregations ----------------
__global__ void agg_vpa() {
    int cnt = g_count[0];
    int nw = gridDim.x * (blockDim.x >> 5);
    int w = blockIdx.x * (blockDim.x >> 5) + (threadIdx.x >> 5);
    int lane = threadIdx.x & 31;
    for (int e = w; e < cnt; e += nw) {
        int2 p = g_elist[0][e];
        float4 a = *(const float4*)(g_x + (size_t)p.x * C + lane * 4);
        float4 b = *(const float4*)(g_x + (size_t)p.y * C + lane * 4);
        unsigned int* o = (unsigned int*)(g_xag + (size_t)p.y * C + lane * 4);
        float m;
        m = a.x + b.x; if (m > 0.f) atomicMax(o + 0, __float_as_uint(m));
        m = a.y + b.y; if (m > 0.f) atomicMax(o + 1, __float_as_uint(m));
        m = a.z + b.z; if (m > 0.f) atomicMax(o + 2, __float_as_uint(m));
        m = a.w + b.w; if (m > 0.f) atomicMax(o + 3, __float_as_uint(m));
    }
}
__global__ void ares_k(const float* __restrict__ fcW, const float* __restrict__ fcb) {
    int n = blockIdx.x * (blockDim.x >> 5) + (threadIdx.x >> 5);
    if (n >= NN) return;
    int lane = threadIdx.x & 31;
    float4 a4 = *(const float4*)(g_a + (size_t)n * C + lane * 4);
    float4 w4 = *(const float4*)(fcW + lane * 4);
    float s = a4.x * w4.x + a4.y * w4.y + a4.z * w4.z + a4.w * w4.w;
#pragma unroll
    for (int o = 16; o; o >>= 1) s += __shfl_xor_sync(0xffffffffu, s, o);
    if (lane == 0) g_ares[n] = s + fcb[0];
}
__global__ void agg_acv() {
    int cnt = g_count[2];
    int nw = gridDim.x * (blockDim.x >> 5);
    int w = blockIdx.x * (blockDim.x >> 5) + (threadIdx.x >> 5);
    int lane = threadIdx.x & 31;
    for (int e = w; e < cnt; e += nw) {
        int2 p = g_elist[2][e];
        float wgt = g_ares[p.x];
        float4 a = *(const float4*)(g_x + (size_t)p.x * C + lane * 4);
        float4 b = *(const float4*)(g_x + (size_t)p.y * C + lane * 4);
        float* o = g_xv2 + (size_t)p.y * C + lane * 4;
        atomicAdd(o + 0, wgt * a.x + b.x);
        atomicAdd(o + 1, wgt * a.y + b.y);
        atomicAdd(o + 2, wgt * a.z + b.z);
        atomicAdd(o + 3, wgt * a.w + b.w);
    }
}
__global__ void agg_sage(int li) {
    int cnt = g_count[li];
    int nw = gridDim.x * (blockDim.x >> 5);
    int w = blockIdx.x * (blockDim.x >> 5) + (threadIdx.x >> 5);
    int lane = threadIdx.x & 31;
    for (int e = w; e < cnt; e += nw) {
        int2 p = g_elist[li][e];
        float4 hv = *(const float4*)(g_h + (size_t)p.x * C + lane * 4);
        float* o = g_s + (size_t)p.y * C + lane * 4;
        atomicAdd(o + 0, hv.x);
        atomicAdd(o + 1, hv.y);
        atomicAdd(o + 2, hv.z);
        atomicAdd(o + 3, hv.w);
    }
}

// ---------------- launch ----------------
extern "C" void kernel_launch(void* const* d_in, const int* in_sizes, int n_in,
                              void* d_out, int out_size) {
    (void)in_sizes; (void)n_in; (void)out_size;
    const float* xv = (const float*)d_in[0];
    const float* xa = (const float*)d_in[1];
    const float* b011 = (const float*)d_in[3];
    const float* b012 = (const float*)d_in[5];
    const float* ecA_b1 = (const float*)d_in[7];
    const float* ecA_b2 = (const float*)d_in[9];
    const float* sage_bl = (const float*)d_in[23];
    const float* fc_W = (const float*)d_in[25];
    const float* fc_b = (const float*)d_in[26];
    const int* edge_index = (const int*)d_in[27];
    const int* edge_attr = (const int*)d_in[28];
    float* out = (float*)d_out;

    WPtrs P;
    P.p[0] = (const float*)d_in[2];
    P.p[1] = (const float*)d_in[4];
    P.p[2] = (const float*)d_in[6];
    P.p[3] = (const float*)d_in[8];
    P.p[4] = (const float*)d_in[10];
    P.p[5] = (const float*)d_in[12];
    P.p[6] = (const float*)d_in[14];
    P.p[7] = (const float*)d_in[16];
    P.p[8] = (const float*)d_in[18];
    P.p[9] = (const float*)d_in[20];
    P.p[10] = (const float*)d_in[22];
    P.p[11] = (const float*)d_in[24];

    cudaFuncSetAttribute(prep_w, cudaFuncAttributeMaxDynamicSharedMemorySize, 128 * 132 * 4);
    cudaFuncSetAttribute(proj_mma, cudaFuncAttributeMaxDynamicSharedMemorySize, SMEM_PROJ);
    cudaFuncSetAttribute(node_dual_mma, cudaFuncAttributeMaxDynamicSharedMemorySize, SMEM_BYTES);
    cudaFuncSetAttribute(edge_mma, cudaFuncAttributeMaxDynamicSharedMemorySize, SMEM_BYTES);
    cudaFuncSetAttribute(final_mma, cudaFuncAttributeMaxDynamicSharedMemorySize, SMEM_BYTES);

    float *pxag, *pxv2, *pa, *pw, *pv, *ph;
    cudaGetSymbolAddress((void**)&pxag, g_xag);
    cudaGetSymbolAddress((void**)&pxv2, g_xv2);
    cudaGetSymbolAddress((void**)&pa, g_a);
    cudaGetSymbolAddress((void**)&pw, g_u);
    cudaGetSymbolAddress((void**)&pv, g_v);
    cudaGetSymbolAddress((void**)&ph, g_h);

    zero_all<<<8192, 256>>>((float4*)d_out);
    prep_w<<<30, 256, 128 * 132 * 4>>>(P);
    classify_k<<<(EE + 255) / 256, 256>>>(edge_index, edge_attr);
    proj_mma<<<NN / 128, 256, SMEM_PROJ>>>(xv, xa, b011, b012);

    agg_vpa<<<2048, 256>>>();

    node_dual_mma<<<NN / 128, 256, SMEM_BYTES>>>(pxag, 16, ecA_b1, pw, pv, 0);
    edge_mma<<<2048, 256, SMEM_BYTES>>>(1, 18, ecA_b2, pw, pv, pa);
    ares_k<<<NN / 8, 256>>>(fc_W, fc_b);

    agg_acv<<<2048, 256>>>();

    for (int k = 0; k < 3; k++) {
        const float* b1 = (const float*)d_in[11 + 4 * k];
        const float* b2 = (const float*)d_in[13 + 4 * k];
        zero_hs<<<8192, 256>>>();
        node_dual_mma<<<NN / 128, 256, SMEM_BYTES>>>(pxv2, 19 + 3 * k, b1, pw, pv, 1);
        edge_mma<<<2048, 256, SMEM_BYTES>>>(3 + k, 21 + 3 * k, b2, pw, pv, ph);
        agg_sage<<<2048, 256>>>(6 + k);
        final_mma<<<MOUT / 128, 256, SMEM_BYTES>>>(sage_bl, k, out);
    }
}